// round 3
// baseline (speedup 1.0000x reference)
#include <cuda_runtime.h>
#include <cuda_bf16.h>
#include <cstdint>

// ---------------------------------------------------------------- constants
#define T_   1024
#define BZ   4
#define E_   1024
#define NH   16
#define HD   64
#define BH   64          // bsz * nh
#define SLEN 1025        // src_len = T + 1 (bias_kv)
#define M_   4096        // T*B rows of the projection GEMMs
#define QSCALE 0.00390625f   // hd^-0.5 / ALPHA = (1/8)/32 = 1/256

// GEMM tiling (mma.sync path)
#define BKB   64         // bytes of K per iter (32 bf16)
#define ROWB  80         // padded smem row bytes (64B data + 16B pad)
#define TILEB (128 * ROWB)        // 10240 B per tile
#define STAGEB (4 * TILEB)        // Ahi Alo Bhi Blo = 40960 B
#define GEMM_SMEM (2 * STAGEB)    // 81920 B

// ---------------------------------------------------------------- scratch
__device__ float g_Q[(size_t)BH * T_ * HD];        // [x][y][d]
__device__ float g_K[(size_t)BH * SLEN * HD];      // [x][yk][d]
__device__ float g_V[(size_t)BH * SLEN * HD];      // [x][yk][d]
__device__ float g_gate[(size_t)BH * T_];          // [x][y]
__device__ float g_pb[(size_t)NH * 2048];          // [h][rel+1023]
__device__ float g_attn[(size_t)M_ * E_];          // (y*4+b, (x%16)*64+d)

__device__ __nv_bfloat16 g_Ahi[(size_t)M_ * E_];   // split A (query, then attn)
__device__ __nv_bfloat16 g_Alo[(size_t)M_ * E_];
__device__ __nv_bfloat16 g_Whi[4][(size_t)E_ * E_];  // transposed weights [n][k]
__device__ __nv_bfloat16 g_Wlo[4][(size_t)E_ * E_];

// ---------------------------------------------------------------- helpers
__device__ __forceinline__ uint32_t cvta_smem(const void* p) {
    uint32_t a;
    asm("{ .reg .u64 t; cvta.to.shared.u64 t, %1; cvt.u32.u64 %0, t; }"
        : "=r"(a) : "l"(p));
    return a;
}

#define CP16(dst, src) \
    asm volatile("cp.async.cg.shared.global [%0], [%1], 16;" \
        :: "r"(dst), "l"(src) : "memory")
#define CPCOMMIT() asm volatile("cp.async.commit_group;" ::: "memory")
#define CPWAIT1()  asm volatile("cp.async.wait_group 1;" ::: "memory")
#define CPWAIT0()  asm volatile("cp.async.wait_group 0;" ::: "memory")

__device__ __forceinline__ void ldsm_x4(uint32_t r[4], uint32_t addr) {
    asm volatile(
        "ldmatrix.sync.aligned.m8n8.x4.shared.b16 {%0,%1,%2,%3}, [%4];"
        : "=r"(r[0]), "=r"(r[1]), "=r"(r[2]), "=r"(r[3]) : "r"(addr));
}

__device__ __forceinline__ void mma16816(float c[4], const uint32_t a[4],
                                         uint32_t b0, uint32_t b1) {
    asm volatile(
        "mma.sync.aligned.m16n8k16.row.col.f32.bf16.bf16.f32 "
        "{%0,%1,%2,%3}, {%4,%5,%6,%7}, {%8,%9}, {%0,%1,%2,%3};"
        : "+f"(c[0]), "+f"(c[1]), "+f"(c[2]), "+f"(c[3])
        : "r"(a[0]), "r"(a[1]), "r"(a[2]), "r"(a[3]), "r"(b0), "r"(b1));
}

// ---------------------------------------------------------------- bf16 split
__global__ __launch_bounds__(256)
void split_kernel(const float* __restrict__ src,
                  __nv_bfloat16* __restrict__ hi,
                  __nv_bfloat16* __restrict__ lo, int n4)
{
    int i = blockIdx.x * blockDim.x + threadIdx.x;
    if (i >= n4) return;
    float4 v = reinterpret_cast<const float4*>(src)[i];
    float x[4] = {v.x, v.y, v.z, v.w};
    __nv_bfloat16 h[4], l[4];
    #pragma unroll
    for (int j = 0; j < 4; j++) {
        h[j] = __float2bfloat16(x[j]);
        l[j] = __float2bfloat16(x[j] - __bfloat162float(h[j]));
    }
    __nv_bfloat162* hp = reinterpret_cast<__nv_bfloat162*>(hi);
    __nv_bfloat162* lp = reinterpret_cast<__nv_bfloat162*>(lo);
    hp[2 * i]     = __nv_bfloat162(h[0], h[1]);
    hp[2 * i + 1] = __nv_bfloat162(h[2], h[3]);
    lp[2 * i]     = __nv_bfloat162(l[0], l[1]);
    lp[2 * i + 1] = __nv_bfloat162(l[2], l[3]);
}

// transpose + split weight: Wt[n][k] = W[k][n]
__global__ __launch_bounds__(256)
void transW_kernel(const float* __restrict__ W,
                   __nv_bfloat16* __restrict__ hi,
                   __nv_bfloat16* __restrict__ lo)
{
    __shared__ float tile[32][33];
    int tx = threadIdx.x, ty = threadIdx.y;          // 32 x 8
    int bx = blockIdx.x * 32, by = blockIdx.y * 32;
    #pragma unroll
    for (int r = 0; r < 4; r++)
        tile[ty + r * 8][tx] = W[(size_t)(by + ty + r * 8) * E_ + bx + tx];
    __syncthreads();
    #pragma unroll
    for (int r = 0; r < 4; r++) {
        int n = bx + ty + r * 8, k = by + tx;
        float v = tile[tx][ty + r * 8];
        __nv_bfloat16 h = __float2bfloat16(v);
        hi[(size_t)n * E_ + k] = h;
        lo[(size_t)n * E_ + k] = __float2bfloat16(v - __bfloat162float(h));
    }
}

// ---------------------------------------------------------------- mma GEMM
// C[4096 or 4096,1024] = A @ W^T(+bias), A[m][k] bf16 split, W stored [n][k].
// MODE 0: Q proj (scale + scrambled scatter)
// MODE 1/2: K/V proj (scrambled scatter)
// MODE 3: out proj -> Cout row-major
template<int MODE>
__global__ __launch_bounds__(256)
void mma_gemm(const __nv_bfloat16* __restrict__ Ahi,
              const __nv_bfloat16* __restrict__ Alo,
              const __nv_bfloat16* __restrict__ Bhi,
              const __nv_bfloat16* __restrict__ Blo,
              const float* __restrict__ bias,
              float* __restrict__ Cout)
{
    extern __shared__ __align__(16) char sm_[];
    const int tid = threadIdx.x, lane = tid & 31, w = tid >> 5;
    const int bn = blockIdx.x, bm = blockIdx.y;
    const uint32_t smem_u = cvta_smem(sm_);

    const __nv_bfloat16* gsrc0 = Ahi + (size_t)(bm * 128) * 1024;
    const __nv_bfloat16* gsrc1 = Alo + (size_t)(bm * 128) * 1024;
    const __nv_bfloat16* gsrc2 = Bhi + (size_t)(bn * 128) * 1024;
    const __nv_bfloat16* gsrc3 = Blo + (size_t)(bn * 128) * 1024;

    const int row0 = tid >> 2, ch0 = tid & 3;           // chunk 0 of this thread
    const int row1 = (tid + 256) >> 2, ch1 = ch0;       // chunk 1

    auto load_stage = [&](int it, int s) {
        uint32_t sb = smem_u + s * STAGEB;
        const int kb = it * BKB;
        const char* g0 = (const char*)gsrc0 + kb;
        const char* g1 = (const char*)gsrc1 + kb;
        const char* g2 = (const char*)gsrc2 + kb;
        const char* g3 = (const char*)gsrc3 + kb;
        uint32_t d0 = sb + row0 * ROWB + ch0 * 16;
        uint32_t d1 = sb + row1 * ROWB + ch1 * 16;
        size_t o0 = (size_t)row0 * 2048 + ch0 * 16;
        size_t o1 = (size_t)row1 * 2048 + ch1 * 16;
        CP16(d0,              g0 + o0); CP16(d1,              g0 + o1);
        CP16(d0 + TILEB,      g1 + o0); CP16(d1 + TILEB,      g1 + o1);
        CP16(d0 + 2 * TILEB,  g2 + o0); CP16(d1 + 2 * TILEB,  g2 + o1);
        CP16(d0 + 3 * TILEB,  g3 + o0); CP16(d1 + 3 * TILEB,  g3 + o1);
        CPCOMMIT();
    };

    float acc[2][8][4] = {};
    const int wm = w & 3, wn = w >> 2;
    const int m0 = wm * 32, n0 = wn * 64;
    const int gid = lane >> 2, tig = lane & 3;
    const int mat = lane >> 3, rowin = lane & 7;

    // ldmatrix per-thread row offsets (within a tile)
    const int a_row = rowin + (mat & 1) * 8;       // + m0 + mt*16
    const int a_kof = (mat >> 1) * 16;             // + ks*32
    const int b_row = rowin + (mat >> 1) * 8;      // + n0 + np*16
    const int b_kof = (mat & 1) * 16;              // + ks*32

    load_stage(0, 0);

    for (int it = 0; it < 32; it++) {
        int s = it & 1;
        if (it + 1 < 32) { load_stage(it + 1, s ^ 1); CPWAIT1(); }
        else             { CPWAIT0(); }
        __syncthreads();
        uint32_t sb = smem_u + s * STAGEB;
        #pragma unroll
        for (int ks = 0; ks < 2; ks++) {
            uint32_t ahi[2][4], alo[2][4];
            #pragma unroll
            for (int mt = 0; mt < 2; mt++) {
                uint32_t ar = sb + (m0 + mt * 16 + a_row) * ROWB
                              + ks * 32 + a_kof;
                ldsm_x4(ahi[mt], ar);
                ldsm_x4(alo[mt], ar + TILEB);
            }
            #pragma unroll
            for (int np = 0; np < 4; np++) {
                uint32_t br = sb + 2 * TILEB
                              + (n0 + np * 16 + b_row) * ROWB
                              + ks * 32 + b_kof;
                uint32_t bhi[4], blo[4];
                ldsm_x4(bhi, br);
                ldsm_x4(blo, br + TILEB);
                #pragma unroll
                for (int h = 0; h < 2; h++) {
                    int nt = np * 2 + h;
                    #pragma unroll
                    for (int mt = 0; mt < 2; mt++) {
                        mma16816(acc[mt][nt], ahi[mt], bhi[2 * h], bhi[2 * h + 1]);
                        mma16816(acc[mt][nt], ahi[mt], blo[2 * h], blo[2 * h + 1]);
                        mma16816(acc[mt][nt], alo[mt], bhi[2 * h], bhi[2 * h + 1]);
                    }
                }
            }
        }
        __syncthreads();
    }

    // ---- epilogue: bias + scatter
    #pragma unroll
    for (int mt = 0; mt < 2; mt++) {
        #pragma unroll
        for (int nt = 0; nt < 8; nt++) {
            int n = bn * 128 + n0 + nt * 8 + tig * 2;
            float bx = bias[n], by = bias[n + 1];
            #pragma unroll
            for (int half = 0; half < 2; half++) {
                int m = bm * 128 + m0 + mt * 16 + gid + half * 8;
                float2 v = make_float2(acc[mt][nt][half * 2 + 0] + bx,
                                       acc[mt][nt][half * 2 + 1] + by);
                if (MODE == 3) {
                    *reinterpret_cast<float2*>(&Cout[(size_t)m * E_ + n]) = v;
                } else {
                    int t = m >> 2, b = m & 3;
                    int h = n >> 6, d = n & 63;
                    if (MODE == 0) {
                        int x = b * 16 + (t >> 6);
                        int y = ((t & 63) << 4) | h;
                        v.x *= QSCALE; v.y *= QSCALE;
                        *reinterpret_cast<float2*>(
                            &g_Q[((size_t)x * T_ + y) * HD + d]) = v;
                    } else {
                        int u = t * 16 + h;
                        int x = b * 16 + u / 1025;
                        int y = u % 1025;
                        float* dst = (MODE == 1) ? g_K : g_V;
                        *reinterpret_cast<float2*>(
                            &dst[((size_t)x * SLEN + y) * HD + d]) = v;
                    }
                }
            }
        }
    }
}

// ---------------------------------------------------------------- small kernels
__global__ void biaskv_kernel(const float* __restrict__ bias_k,
                              const float* __restrict__ bias_v)
{
    int i = blockIdx.x * blockDim.x + threadIdx.x;
    if (i >= BZ * NH * HD) return;
    int b = i >> 10, h = (i >> 6) & 15, d = i & 63;
    int x = b * 16 + 15;
    int y = 1009 + h;
    g_K[((size_t)x * SLEN + y) * HD + d] = bias_k[h * HD + d];
    g_V[((size_t)x * SLEN + y) * HD + d] = bias_v[h * HD + d];
}

__global__ void pb_kernel(const float* __restrict__ rel_emb)
{
    int d = blockIdx.x * blockDim.x + threadIdx.x;
    if (d >= 2048) return;
    int rel = d - 1023;
    int bkt = rel > 0 ? 16 : 0;
    int a = rel < 0 ? -rel : rel;
    int bu;
    if (a < 8) {
        bu = a;
    } else {
        float lf = logf((float)a * 0.125f + 1e-6f) * (8.0f / 2.772588722239781f);
        int large = 8 + (int)lf;
        bu = large < 15 ? large : 15;
    }
    int bucket = bkt + bu;
    #pragma unroll
    for (int h = 0; h < NH; h++)
        g_pb[h * 2048 + d] = rel_emb[bucket * NH + h];
}

__global__ __launch_bounds__(256)
void gate_kernel(const float* __restrict__ grep_w,
                 const float* __restrict__ grep_b,
                 const float* __restrict__ grep_a)
{
    __shared__ float gws[64];
    __shared__ float gbs;
    int tid = threadIdx.x;
    if (tid < 64) {
        float s = 0.f;
        #pragma unroll
        for (int j = 0; j < 8; j++) s += grep_w[tid * 8 + j];
        gws[tid] = s;
    }
    if (tid == 64) {
        float s = 0.f;
        #pragma unroll
        for (int j = 0; j < 8; j++) s += grep_b[j];
        gbs = s;
    }
    __syncthreads();
    int warp = tid >> 5, lane = tid & 31;
    int row = blockIdx.x * 8 + warp;
    if (row < BH * T_) {
        const float* q = &g_Q[(size_t)row * HD];
        float s = q[lane] * gws[lane] + q[lane + 32] * gws[lane + 32];
        #pragma unroll
        for (int off = 16; off; off >>= 1)
            s += __shfl_xor_sync(0xffffffffu, s, off);
        if (lane == 0) {
            int hx = (row >> 10) & 15;
            float val = s * 256.0f + gbs;
            float sig = 1.0f / (1.0f + __expf(-val));
            g_gate[row] = sig * grep_a[hx];
        }
    }
}

// ---------------------------------------------------------------- attention
#define SATT 68
__global__ __launch_bounds__(256)
void attn_kernel()
{
    extern __shared__ float sm[];
    float* Qs   = sm;
    float* Ks   = Qs + 64 * SATT;
    float* Vs   = Ks + 64 * SATT;
    float* Ss   = Vs + 64 * SATT;
    float* red  = Ss + 64 * SATT;
    float* m_s  = red + 256;
    float* l_s  = m_s + 64;
    float* al_s = l_s + 64;
    float* gt_s = al_s + 64;

    int tid = threadIdx.x;
    int x   = blockIdx.y;
    int t0  = blockIdx.x * 64;
    int hx  = x & 15;
    int bx  = x >> 4;

    #pragma unroll
    for (int it = 0; it < 4; it++) {
        int q = tid + it * 256;
        int r = q >> 4;
        int dd = (q & 15) * 4;
        float4 v = *(const float4*)&g_Q[((size_t)x * T_ + t0 + r) * HD + dd];
        Qs[(dd + 0) * SATT + r] = v.x; Qs[(dd + 1) * SATT + r] = v.y;
        Qs[(dd + 2) * SATT + r] = v.z; Qs[(dd + 3) * SATT + r] = v.w;
    }
    if (tid < 64) {
        gt_s[tid] = g_gate[(size_t)x * T_ + t0 + tid];
        m_s[tid] = -1e30f;
        l_s[tid] = 0.f;
    }
    __syncthreads();

    int tr = tid >> 4, tc = tid & 15;
    int r0 = tr * 4, c0 = tc * 4;
    float o[4][4] = {};
    float gate_r[4];
    #pragma unroll
    for (int i = 0; i < 4; i++) gate_r[i] = gt_s[r0 + i];

    for (int ch = 0; ch < 17; ch++) {
        int s0 = ch * 64;
        #pragma unroll
        for (int it = 0; it < 4; it++) {
            int q = tid + it * 256;
            int s = q >> 4;
            int dd = (q & 15) * 4;
            int sg = s0 + s;
            float4 kv = make_float4(0.f, 0.f, 0.f, 0.f);
            float4 vv = make_float4(0.f, 0.f, 0.f, 0.f);
            if (sg < SLEN) {
                kv = *(const float4*)&g_K[((size_t)x * SLEN + sg) * HD + dd];
                vv = *(const float4*)&g_V[((size_t)x * SLEN + sg) * HD + dd];
            }
            Ks[(dd + 0) * SATT + s] = kv.x; Ks[(dd + 1) * SATT + s] = kv.y;
            Ks[(dd + 2) * SATT + s] = kv.z; Ks[(dd + 3) * SATT + s] = kv.w;
            *(float4*)&Vs[s * SATT + dd] = vv;
        }
        __syncthreads();

        float sacc[4][4] = {};
        #pragma unroll
        for (int k = 0; k < 64; k++) {
            float a[4], bb[4];
            *(float4*)a  = *(float4*)&Qs[k * SATT + r0];
            *(float4*)bb = *(float4*)&Ks[k * SATT + c0];
            #pragma unroll
            for (int i = 0; i < 4; i++)
                #pragma unroll
                for (int j = 0; j < 4; j++)
                    sacc[i][j] += a[i] * bb[j];
        }
        #pragma unroll
        for (int j = 0; j < 4; j++) {
            int sg = s0 + c0 + j;
            #pragma unroll
            for (int i = 0; i < 4; i++) {
                float val;
                if (sg < SLEN) {
                    int tg = t0 + r0 + i;
                    val = sacc[i][j] +
                          gate_r[i] * g_pb[hx * 2048 + (sg - tg + 1023)];
                } else {
                    val = -1e30f;
                }
                Ss[(c0 + j) * SATT + (r0 + i)] = val;
            }
        }
        __syncthreads();

        {
            int r = tid & 63, part = tid >> 6;
            float pm = -1e30f;
            #pragma unroll
            for (int i = 0; i < 16; i++)
                pm = fmaxf(pm, Ss[(part * 16 + i) * SATT + r]);
            red[part * 64 + r] = pm;
        }
        __syncthreads();
        if (tid < 64) {
            int r = tid;
            float mo = m_s[r];
            float cm = fmaxf(fmaxf(red[r], red[64 + r]),
                             fmaxf(red[128 + r], red[192 + r]));
            float mn = fmaxf(mo, cm);
            al_s[r] = __expf(mo - mn);
            m_s[r] = mn;
        }
        __syncthreads();
        {
            int r = tid & 63, part = tid >> 6;
            float mn = m_s[r];
            float ps = 0.f;
            #pragma unroll
            for (int i = 0; i < 16; i++) {
                float p = __expf(Ss[(part * 16 + i) * SATT + r] - mn);
                Ss[(part * 16 + i) * SATT + r] = p;
                ps += p;
            }
            red[part * 64 + r] = ps;
        }
        __syncthreads();
        if (tid < 64) {
            int r = tid;
            l_s[r] = l_s[r] * al_s[r] +
                     red[r] + red[64 + r] + red[128 + r] + red[192 + r];
        }
        __syncthreads();

        #pragma unroll
        for (int i = 0; i < 4; i++) {
            float a = al_s[r0 + i];
            #pragma unroll
            for (int j = 0; j < 4; j++) o[i][j] *= a;
        }
        #pragma unroll
        for (int k = 0; k < 64; k++) {
            float p[4], vv[4];
            *(float4*)p  = *(float4*)&Ss[k * SATT + r0];
            *(float4*)vv = *(float4*)&Vs[k * SATT + c0];
            #pragma unroll
            for (int i = 0; i < 4; i++)
                #pragma unroll
                for (int j = 0; j < 4; j++)
                    o[i][j] += p[i] * vv[j];
        }
        __syncthreads();
    }

    #pragma unroll
    for (int i = 0; i < 4; i++) {
        int y = t0 + r0 + i;
        float inv = 1.0f / l_s[r0 + i];
        #pragma unroll
        for (int j = 0; j < 4; j++) {
            g_attn[((size_t)(y * BZ + bx)) * E_ + hx * HD + c0 + j] =
                o[i][j] * inv;
        }
    }
}

// ---------------------------------------------------------------- host side
extern "C" void kernel_launch(void* const* d_in, const int* in_sizes, int n_in,
                              void* d_out, int out_size)
{
    (void)in_sizes; (void)n_in; (void)out_size;
    const float* query   = (const float*)d_in[0];
    const float* q_w     = (const float*)d_in[1];
    const float* q_b     = (const float*)d_in[2];
    const float* k_w     = (const float*)d_in[3];
    const float* k_b     = (const float*)d_in[4];
    const float* v_w     = (const float*)d_in[5];
    const float* v_b     = (const float*)d_in[6];
    const float* out_w   = (const float*)d_in[7];
    const float* out_b   = (const float*)d_in[8];
    const float* rel_emb = (const float*)d_in[9];
    const float* grep_w  = (const float*)d_in[10];
    const float* grep_b  = (const float*)d_in[11];
    const float* grep_a  = (const float*)d_in[12];
    const float* bias_k  = (const float*)d_in[13];
    const float* bias_v  = (const float*)d_in[14];
    float* out = (float*)d_out;

    void *pAhi, *pAlo, *pWhi, *pWlo, *pAttn;
    cudaGetSymbolAddress(&pAhi,  g_Ahi);
    cudaGetSymbolAddress(&pAlo,  g_Alo);
    cudaGetSymbolAddress(&pWhi,  g_Whi);
    cudaGetSymbolAddress(&pWlo,  g_Wlo);
    cudaGetSymbolAddress(&pAttn, g_attn);

    __nv_bfloat16* Ahi = (__nv_bfloat16*)pAhi;
    __nv_bfloat16* Alo = (__nv_bfloat16*)pAlo;
    const size_t wsz = (size_t)E_ * E_;
    __nv_bfloat16* Whi = (__nv_bfloat16*)pWhi;
    __nv_bfloat16* Wlo = (__nv_bfloat16*)pWlo;

    cudaFuncSetAttribute((const void*)mma_gemm<0>,
        cudaFuncAttributeMaxDynamicSharedMemorySize, GEMM_SMEM);
    cudaFuncSetAttribute((const void*)mma_gemm<1>,
        cudaFuncAttributeMaxDynamicSharedMemorySize, GEMM_SMEM);
    cudaFuncSetAttribute((const void*)mma_gemm<2>,
        cudaFuncAttributeMaxDynamicSharedMemorySize, GEMM_SMEM);
    cudaFuncSetAttribute((const void*)mma_gemm<3>,
        cudaFuncAttributeMaxDynamicSharedMemorySize, GEMM_SMEM);

    dim3 tgrid(32, 32), tblock(32, 8);
    dim3 ggrid(E_ / 128, M_ / 128);    // (8, 32)

    // split A (= query), transpose+split weights
    split_kernel<<<4096, 256>>>(query, Ahi, Alo, M_ * E_ / 4);
    transW_kernel<<<tgrid, tblock>>>(q_w,   Whi + 0 * wsz, Wlo + 0 * wsz);
    transW_kernel<<<tgrid, tblock>>>(k_w,   Whi + 1 * wsz, Wlo + 1 * wsz);
    transW_kernel<<<tgrid, tblock>>>(v_w,   Whi + 2 * wsz, Wlo + 2 * wsz);
    transW_kernel<<<tgrid, tblock>>>(out_w, Whi + 3 * wsz, Wlo + 3 * wsz);

    // projections
    mma_gemm<0><<<ggrid, 256, GEMM_SMEM>>>(Ahi, Alo, Whi + 0 * wsz, Wlo + 0 * wsz, q_b, nullptr);
    mma_gemm<1><<<ggrid, 256, GEMM_SMEM>>>(Ahi, Alo, Whi + 1 * wsz, Wlo + 1 * wsz, k_b, nullptr);
    mma_gemm<2><<<ggrid, 256, GEMM_SMEM>>>(Ahi, Alo, Whi + 2 * wsz, Wlo + 2 * wsz, v_b, nullptr);

    biaskv_kernel<<<16, 256>>>(bias_k, bias_v);
    pb_kernel<<<8, 256>>>(rel_emb);
    gate_kernel<<<8192, 256>>>(grep_w, grep_b, grep_a);

    int attn_smem = (4 * 64 * SATT + 256 + 4 * 64) * (int)sizeof(float);
    cudaFuncSetAttribute((const void*)attn_kernel,
                         cudaFuncAttributeMaxDynamicSharedMemorySize, attn_smem);
    attn_kernel<<<dim3(16, 64), 256, attn_smem>>>();

    // out projection: split attn result, then GEMM into d_out
    split_kernel<<<4096, 256>>>((const float*)pAttn, Ahi, Alo, M_ * E_ / 4);
    mma_gemm<3><<<ggrid, 256, GEMM_SMEM>>>(Ahi, Alo, Whi + 3 * wsz, Wlo + 3 * wsz, out_b, out);
}

// round 4
// speedup vs baseline: 2.6157x; 2.6157x over previous
#include <cuda_runtime.h>
#include <cuda_bf16.h>
#include <cstdint>

// ---------------------------------------------------------------- constants
#define T_   1024
#define BZ   4
#define E_   1024
#define NH   16
#define HD   64
#define BH   64          // bsz * nh
#define SLEN 1025        // src_len = T + 1 (bias_kv)
#define M_   4096        // T*B rows of the projection GEMMs
#define QSCALE 0.00390625f   // hd^-0.5 / ALPHA = (1/8)/32 = 1/256

// GEMM tiling (mma.sync path)
#define BKB   64         // bytes of K per iter (32 bf16)
#define ROWB  80         // padded smem row bytes (64B data + 16B pad)
#define TILEB (128 * ROWB)        // 10240 B per tile
#define STAGEB (4 * TILEB)        // Ahi Alo Bhi Blo = 40960 B
#define GEMM_SMEM (2 * STAGEB)    // 81920 B

// attention smem
#define AROW  144                 // 128B data + 16B pad
#define ATILE (64 * AROW)         // 9216 B
#define A_QH  0
#define A_QL  ATILE
#define A_ST  (2 * ATILE)         // stage base
#define A_STB (4 * ATILE)         // KH KL VH VL per stage
#define ATTN_SMEM (A_ST + 2 * A_STB)   // 92160 B

#define KVSZ ((size_t)BH * SLEN * HD + 8192)   // slack for chunk-16 overread

// ---------------------------------------------------------------- scratch
__device__ float g_Qf[(size_t)BH * T_ * HD];          // f32 Q (gate input)
__device__ __nv_bfloat16 g_Qh[(size_t)BH * T_ * HD];
__device__ __nv_bfloat16 g_Ql[(size_t)BH * T_ * HD];
__device__ __nv_bfloat16 g_Kh[KVSZ], g_Kl[KVSZ];
__device__ __nv_bfloat16 g_Vh[KVSZ], g_Vl[KVSZ];
__device__ float g_gate[(size_t)BH * T_];
__device__ float g_pb[(size_t)NH * 2048];

__device__ __nv_bfloat16 g_Ahi[(size_t)M_ * E_];   // GEMM A (query, then O)
__device__ __nv_bfloat16 g_Alo[(size_t)M_ * E_];
__device__ __nv_bfloat16 g_Whi[4][(size_t)E_ * E_];
__device__ __nv_bfloat16 g_Wlo[4][(size_t)E_ * E_];

// ---------------------------------------------------------------- helpers
__device__ __forceinline__ uint32_t cvta_smem(const void* p) {
    uint32_t a;
    asm("{ .reg .u64 t; cvta.to.shared.u64 t, %1; cvt.u32.u64 %0, t; }"
        : "=r"(a) : "l"(p));
    return a;
}

#define CP16(dst, src) \
    asm volatile("cp.async.cg.shared.global [%0], [%1], 16;" \
        :: "r"(dst), "l"(src) : "memory")
#define CPCOMMIT() asm volatile("cp.async.commit_group;" ::: "memory")
#define CPWAIT1()  asm volatile("cp.async.wait_group 1;" ::: "memory")
#define CPWAIT0()  asm volatile("cp.async.wait_group 0;" ::: "memory")

__device__ __forceinline__ void ldsm_x4(uint32_t r[4], uint32_t addr) {
    asm volatile(
        "ldmatrix.sync.aligned.m8n8.x4.shared.b16 {%0,%1,%2,%3}, [%4];"
        : "=r"(r[0]), "=r"(r[1]), "=r"(r[2]), "=r"(r[3]) : "r"(addr));
}
__device__ __forceinline__ void ldsm_x4_t(uint32_t r[4], uint32_t addr) {
    asm volatile(
        "ldmatrix.sync.aligned.m8n8.x4.trans.shared.b16 {%0,%1,%2,%3}, [%4];"
        : "=r"(r[0]), "=r"(r[1]), "=r"(r[2]), "=r"(r[3]) : "r"(addr));
}

__device__ __forceinline__ void mma16816(float c[4], const uint32_t a[4],
                                         uint32_t b0, uint32_t b1) {
    asm volatile(
        "mma.sync.aligned.m16n8k16.row.col.f32.bf16.bf16.f32 "
        "{%0,%1,%2,%3}, {%4,%5,%6,%7}, {%8,%9}, {%0,%1,%2,%3};"
        : "+f"(c[0]), "+f"(c[1]), "+f"(c[2]), "+f"(c[3])
        : "r"(a[0]), "r"(a[1]), "r"(a[2]), "r"(a[3]), "r"(b0), "r"(b1));
}

__device__ __forceinline__ uint32_t packbf(__nv_bfloat16 a, __nv_bfloat16 b) {
    __nv_bfloat162 t(a, b);
    return *reinterpret_cast<uint32_t*>(&t);
}

// split (x,y) into hi/lo packed u32
__device__ __forceinline__ void split2(float x, float y,
                                       uint32_t& hi, uint32_t& lo) {
    __nv_bfloat16 hx = __float2bfloat16(x);
    __nv_bfloat16 hy = __float2bfloat16(y);
    __nv_bfloat16 lx = __float2bfloat16(x - __bfloat162float(hx));
    __nv_bfloat16 ly = __float2bfloat16(y - __bfloat162float(hy));
    hi = packbf(hx, hy);
    lo = packbf(lx, ly);
}

// ---------------------------------------------------------------- bf16 split
__global__ __launch_bounds__(256)
void split_kernel(const float* __restrict__ src,
                  __nv_bfloat16* __restrict__ hi,
                  __nv_bfloat16* __restrict__ lo, int n4)
{
    int i = blockIdx.x * blockDim.x + threadIdx.x;
    if (i >= n4) return;
    float4 v = reinterpret_cast<const float4*>(src)[i];
    uint32_t h0, l0, h1, l1;
    split2(v.x, v.y, h0, l0);
    split2(v.z, v.w, h1, l1);
    uint32_t* hp = reinterpret_cast<uint32_t*>(hi);
    uint32_t* lp = reinterpret_cast<uint32_t*>(lo);
    hp[2 * i] = h0; hp[2 * i + 1] = h1;
    lp[2 * i] = l0; lp[2 * i + 1] = l1;
}

// transpose + split weight: Wt[n][k] = W[k][n]
__global__ __launch_bounds__(256)
void transW_kernel(const float* __restrict__ W,
                   __nv_bfloat16* __restrict__ hi,
                   __nv_bfloat16* __restrict__ lo)
{
    __shared__ float tile[32][33];
    int tx = threadIdx.x, ty = threadIdx.y;          // 32 x 8
    int bx = blockIdx.x * 32, by = blockIdx.y * 32;
    #pragma unroll
    for (int r = 0; r < 4; r++)
        tile[ty + r * 8][tx] = W[(size_t)(by + ty + r * 8) * E_ + bx + tx];
    __syncthreads();
    #pragma unroll
    for (int r = 0; r < 4; r++) {
        int n = bx + ty + r * 8, k = by + tx;
        float v = tile[tx][ty + r * 8];
        __nv_bfloat16 h = __float2bfloat16(v);
        hi[(size_t)n * E_ + k] = h;
        lo[(size_t)n * E_ + k] = __float2bfloat16(v - __bfloat162float(h));
    }
}

// ---------------------------------------------------------------- mma GEMM
// MODE 0: Q proj -> g_Qf (f32, scaled) + g_Qh/g_Ql (bf16 split, scaled)
// MODE 1: K proj -> g_Kh/g_Kl ; MODE 2: V proj -> g_Vh/g_Vl
// MODE 3: out proj -> Cout f32 row-major
template<int MODE>
__global__ __launch_bounds__(256)
void mma_gemm(const __nv_bfloat16* __restrict__ Ahi,
              const __nv_bfloat16* __restrict__ Alo,
              const __nv_bfloat16* __restrict__ Bhi,
              const __nv_bfloat16* __restrict__ Blo,
              const float* __restrict__ bias,
              float* __restrict__ Cout)
{
    extern __shared__ __align__(16) char sm_[];
    const int tid = threadIdx.x, lane = tid & 31, w = tid >> 5;
    const int bn = blockIdx.x, bm = blockIdx.y;
    const uint32_t smem_u = cvta_smem(sm_);

    const __nv_bfloat16* gsrc0 = Ahi + (size_t)(bm * 128) * 1024;
    const __nv_bfloat16* gsrc1 = Alo + (size_t)(bm * 128) * 1024;
    const __nv_bfloat16* gsrc2 = Bhi + (size_t)(bn * 128) * 1024;
    const __nv_bfloat16* gsrc3 = Blo + (size_t)(bn * 128) * 1024;

    const int row0 = tid >> 2, ch0 = tid & 3;
    const int row1 = (tid + 256) >> 2;

    auto load_stage = [&](int it, int s) {
        uint32_t sb = smem_u + s * STAGEB;
        const int kb = it * BKB;
        const char* g0 = (const char*)gsrc0 + kb;
        const char* g1 = (const char*)gsrc1 + kb;
        const char* g2 = (const char*)gsrc2 + kb;
        const char* g3 = (const char*)gsrc3 + kb;
        uint32_t d0 = sb + row0 * ROWB + ch0 * 16;
        uint32_t d1 = sb + row1 * ROWB + ch0 * 16;
        size_t o0 = (size_t)row0 * 2048 + ch0 * 16;
        size_t o1 = (size_t)row1 * 2048 + ch0 * 16;
        CP16(d0,              g0 + o0); CP16(d1,              g0 + o1);
        CP16(d0 + TILEB,      g1 + o0); CP16(d1 + TILEB,      g1 + o1);
        CP16(d0 + 2 * TILEB,  g2 + o0); CP16(d1 + 2 * TILEB,  g2 + o1);
        CP16(d0 + 3 * TILEB,  g3 + o0); CP16(d1 + 3 * TILEB,  g3 + o1);
        CPCOMMIT();
    };

    float acc[2][8][4] = {};
    const int wm = w & 3, wn = w >> 2;
    const int m0 = wm * 32, n0 = wn * 64;
    const int gid = lane >> 2, tig = lane & 3;
    const int mat = lane >> 3, rowin = lane & 7;

    const int a_row = rowin + (mat & 1) * 8;
    const int a_kof = (mat >> 1) * 16;
    const int b_row = rowin + (mat >> 1) * 8;
    const int b_kof = (mat & 1) * 16;

    load_stage(0, 0);

    for (int it = 0; it < 32; it++) {
        int s = it & 1;
        if (it + 1 < 32) { load_stage(it + 1, s ^ 1); CPWAIT1(); }
        else             { CPWAIT0(); }
        __syncthreads();
        uint32_t sb = smem_u + s * STAGEB;
        #pragma unroll
        for (int ks = 0; ks < 2; ks++) {
            uint32_t ahi[2][4], alo[2][4];
            #pragma unroll
            for (int mt = 0; mt < 2; mt++) {
                uint32_t ar = sb + (m0 + mt * 16 + a_row) * ROWB
                              + ks * 32 + a_kof;
                ldsm_x4(ahi[mt], ar);
                ldsm_x4(alo[mt], ar + TILEB);
            }
            #pragma unroll
            for (int np = 0; np < 4; np++) {
                uint32_t br = sb + 2 * TILEB
                              + (n0 + np * 16 + b_row) * ROWB
                              + ks * 32 + b_kof;
                uint32_t bhi[4], blo[4];
                ldsm_x4(bhi, br);
                ldsm_x4(blo, br + TILEB);
                #pragma unroll
                for (int h = 0; h < 2; h++) {
                    int nt = np * 2 + h;
                    #pragma unroll
                    for (int mt = 0; mt < 2; mt++) {
                        mma16816(acc[mt][nt], ahi[mt], bhi[2 * h], bhi[2 * h + 1]);
                        mma16816(acc[mt][nt], ahi[mt], blo[2 * h], blo[2 * h + 1]);
                        mma16816(acc[mt][nt], alo[mt], bhi[2 * h], bhi[2 * h + 1]);
                    }
                }
            }
        }
        __syncthreads();
    }

    // ---- epilogue
    #pragma unroll
    for (int mt = 0; mt < 2; mt++) {
        #pragma unroll
        for (int nt = 0; nt < 8; nt++) {
            int n = bn * 128 + n0 + nt * 8 + tig * 2;
            float bx = bias[n], by = bias[n + 1];
            #pragma unroll
            for (int half = 0; half < 2; half++) {
                int m = bm * 128 + m0 + mt * 16 + gid + half * 8;
                float vx = acc[mt][nt][half * 2 + 0] + bx;
                float vy = acc[mt][nt][half * 2 + 1] + by;
                if (MODE == 3) {
                    *reinterpret_cast<float2*>(&Cout[(size_t)m * E_ + n]) =
                        make_float2(vx, vy);
                } else {
                    int t = m >> 2, b = m & 3;
                    int h = n >> 6, d = n & 63;
                    size_t idx;
                    if (MODE == 0) {
                        int x = b * 16 + (t >> 6);
                        int y = ((t & 63) << 4) | h;
                        idx = ((size_t)x * T_ + y) * HD + d;
                        vx *= QSCALE; vy *= QSCALE;
                        *reinterpret_cast<float2*>(&g_Qf[idx]) =
                            make_float2(vx, vy);
                    } else {
                        int u = t * 16 + h;
                        int x = b * 16 + u / 1025;
                        int y = u % 1025;
                        idx = ((size_t)x * SLEN + y) * HD + d;
                    }
                    uint32_t hi, lo;
                    split2(vx, vy, hi, lo);
                    __nv_bfloat16* ph = (MODE == 0) ? g_Qh : (MODE == 1) ? g_Kh : g_Vh;
                    __nv_bfloat16* pl = (MODE == 0) ? g_Ql : (MODE == 1) ? g_Kl : g_Vl;
                    *reinterpret_cast<uint32_t*>(&ph[idx]) = hi;
                    *reinterpret_cast<uint32_t*>(&pl[idx]) = lo;
                }
            }
        }
    }
}

// ---------------------------------------------------------------- small kernels
__global__ void biaskv_kernel(const float* __restrict__ bias_k,
                              const float* __restrict__ bias_v)
{
    int i = blockIdx.x * blockDim.x + threadIdx.x;
    if (i >= BZ * NH * HD) return;
    int b = i >> 10, h = (i >> 6) & 15, d = i & 63;
    int x = b * 16 + 15;
    int y = 1009 + h;
    size_t idx = ((size_t)x * SLEN + y) * HD + d;
    float kv = bias_k[h * HD + d];
    float vv = bias_v[h * HD + d];
    __nv_bfloat16 kh = __float2bfloat16(kv);
    __nv_bfloat16 vh = __float2bfloat16(vv);
    g_Kh[idx] = kh; g_Kl[idx] = __float2bfloat16(kv - __bfloat162float(kh));
    g_Vh[idx] = vh; g_Vl[idx] = __float2bfloat16(vv - __bfloat162float(vh));
}

__global__ void pb_kernel(const float* __restrict__ rel_emb)
{
    int d = blockIdx.x * blockDim.x + threadIdx.x;
    if (d >= 2048) return;
    int rel = d - 1023;
    int bkt = rel > 0 ? 16 : 0;
    int a = rel < 0 ? -rel : rel;
    int bu;
    if (a < 8) {
        bu = a;
    } else {
        float lf = logf((float)a * 0.125f + 1e-6f) * (8.0f / 2.772588722239781f);
        int large = 8 + (int)lf;
        bu = large < 15 ? large : 15;
    }
    int bucket = bkt + bu;
    #pragma unroll
    for (int h = 0; h < NH; h++)
        g_pb[h * 2048 + d] = rel_emb[bucket * NH + h];
}

__global__ __launch_bounds__(256)
void gate_kernel(const float* __restrict__ grep_w,
                 const float* __restrict__ grep_b,
                 const float* __restrict__ grep_a)
{
    __shared__ float gws[64];
    __shared__ float gbs;
    int tid = threadIdx.x;
    if (tid < 64) {
        float s = 0.f;
        #pragma unroll
        for (int j = 0; j < 8; j++) s += grep_w[tid * 8 + j];
        gws[tid] = s;
    }
    if (tid == 64) {
        float s = 0.f;
        #pragma unroll
        for (int j = 0; j < 8; j++) s += grep_b[j];
        gbs = s;
    }
    __syncthreads();
    int warp = tid >> 5, lane = tid & 31;
    int row = blockIdx.x * 8 + warp;
    if (row < BH * T_) {
        const float* q = &g_Qf[(size_t)row * HD];
        float s = q[lane] * gws[lane] + q[lane + 32] * gws[lane + 32];
        #pragma unroll
        for (int off = 16; off; off >>= 1)
            s += __shfl_xor_sync(0xffffffffu, s, off);
        if (lane == 0) {
            int hx = (row >> 10) & 15;
            float val = s * 256.0f + gbs;
            float sig = 1.0f / (1.0f + __expf(-val));
            g_gate[row] = sig * grep_a[hx];
        }
    }
}

// ---------------------------------------------------------------- attention (mma)
// 64 q-rows per CTA, 128 threads (4 warps, 16 rows each), 17 chunks of 64 keys.
__global__ __launch_bounds__(128)
void attn_mma()
{
    extern __shared__ __align__(16) char asmm[];
    const uint32_t smem_u = cvta_smem(asmm);
    const int tid = threadIdx.x, lane = tid & 31, w = tid >> 5;
    const int gid = lane >> 2, tig = lane & 3;
    const int mat = lane >> 3, rowin = lane & 7;
    const int x = blockIdx.y, t0 = blockIdx.x * 64;
    const int hx = x & 15, bx = x >> 4;

    // ---- Q tile load (one cp.async group)
    {
        const char* srcH = (const char*)g_Qh + ((size_t)x * T_ + t0) * HD * 2;
        const char* srcL = (const char*)g_Ql + ((size_t)x * T_ + t0) * HD * 2;
        #pragma unroll
        for (int i = 0; i < 8; i++) {
            int idx = tid + i * 128;
            int tile = idx >> 9, row = (idx >> 3) & 63, c = idx & 7;
            const char* s = (tile ? srcL : srcH) + (size_t)row * 128 + c * 16;
            uint32_t d = smem_u + (tile ? A_QL : A_QH) + row * AROW + c * 16;
            CP16(d, s);
        }
        CPCOMMIT();
    }

    const char* pKh = (const char*)g_Kh + (size_t)x * SLEN * HD * 2;
    const char* pKl = (const char*)g_Kl + (size_t)x * SLEN * HD * 2;
    const char* pVh = (const char*)g_Vh + (size_t)x * SLEN * HD * 2;
    const char* pVl = (const char*)g_Vl + (size_t)x * SLEN * HD * 2;

    auto load_kv = [&](int ch, int buf) {
        int s0 = ch * 64;
        #pragma unroll
        for (int i = 0; i < 16; i++) {
            int idx = tid + i * 128;
            int tile = idx >> 9, row = (idx >> 3) & 63, c = idx & 7;
            const char* p = (tile & 2) ? ((tile & 1) ? pVl : pVh)
                                       : ((tile & 1) ? pKl : pKh);
            uint32_t d = smem_u + A_ST + buf * A_STB + tile * ATILE
                         + row * AROW + c * 16;
            CP16(d, p + ((size_t)(s0 + row)) * 128 + c * 16);
        }
        CPCOMMIT();
    };

    load_kv(0, 0);

    float m0 = -1e30f, m1 = -1e30f, l0 = 0.f, l1 = 0.f;
    float o[8][4] = {};
    uint32_t qh[4][4], ql[4][4];
    const int tg0 = t0 + w * 16 + gid;
    const float gate0 = g_gate[(size_t)x * T_ + tg0];
    const float gate1 = g_gate[(size_t)x * T_ + tg0 + 8];

    for (int ch = 0; ch < 17; ch++) {
        int buf = ch & 1;
        if (ch + 1 < 17) { load_kv(ch + 1, buf ^ 1); CPWAIT1(); }
        else             { CPWAIT0(); }
        __syncthreads();

        if (ch == 0) {
            #pragma unroll
            for (int ks = 0; ks < 4; ks++) {
                uint32_t qa = smem_u + A_QH
                    + (w * 16 + rowin + (mat & 1) * 8) * AROW
                    + ks * 32 + (mat >> 1) * 16;
                ldsm_x4(qh[ks], qa);
                ldsm_x4(ql[ks], qa + ATILE);
            }
        }

        const uint32_t kb = smem_u + A_ST + buf * A_STB;

        // ---- S = Q K^T (bf16x3)
        float s_acc[8][4] = {};
        #pragma unroll
        for (int ks = 0; ks < 4; ks++) {
            #pragma unroll
            for (int np = 0; np < 4; np++) {
                uint32_t ka = kb + (np * 16 + rowin + (mat >> 1) * 8) * AROW
                              + ks * 32 + (mat & 1) * 16;
                uint32_t khf[4], klf[4];
                ldsm_x4(khf, ka);
                ldsm_x4(klf, ka + ATILE);
                #pragma unroll
                for (int h2 = 0; h2 < 2; h2++) {
                    int nt = np * 2 + h2;
                    mma16816(s_acc[nt], qh[ks], khf[2 * h2], khf[2 * h2 + 1]);
                    mma16816(s_acc[nt], qh[ks], klf[2 * h2], klf[2 * h2 + 1]);
                    mma16816(s_acc[nt], ql[ks], khf[2 * h2], khf[2 * h2 + 1]);
                }
            }
        }

        // ---- gated position bias + mask
        int s0 = ch * 64;
        #pragma unroll
        for (int nt = 0; nt < 8; nt++) {
            #pragma unroll
            for (int j = 0; j < 4; j++) {
                int sg = s0 + nt * 8 + tig * 2 + (j & 1);
                int tg = tg0 + (j >> 1) * 8;
                float g = (j >> 1) ? gate1 : gate0;
                if (sg < SLEN)
                    s_acc[nt][j] += g * __ldg(&g_pb[hx * 2048 + sg - tg + 1023]);
                else
                    s_acc[nt][j] = -1e30f;
            }
        }

        // ---- online softmax (registers)
        float mx0 = -1e30f, mx1 = -1e30f;
        #pragma unroll
        for (int nt = 0; nt < 8; nt++) {
            mx0 = fmaxf(mx0, fmaxf(s_acc[nt][0], s_acc[nt][1]));
            mx1 = fmaxf(mx1, fmaxf(s_acc[nt][2], s_acc[nt][3]));
        }
        mx0 = fmaxf(mx0, __shfl_xor_sync(0xffffffffu, mx0, 1));
        mx0 = fmaxf(mx0, __shfl_xor_sync(0xffffffffu, mx0, 2));
        mx1 = fmaxf(mx1, __shfl_xor_sync(0xffffffffu, mx1, 1));
        mx1 = fmaxf(mx1, __shfl_xor_sync(0xffffffffu, mx1, 2));
        float mn0 = fmaxf(m0, mx0), mn1 = fmaxf(m1, mx1);
        float al0 = __expf(m0 - mn0), al1 = __expf(m1 - mn1);
        m0 = mn0; m1 = mn1;

        float sum0 = 0.f, sum1 = 0.f;
        #pragma unroll
        for (int nt = 0; nt < 8; nt++) {
            float p0 = __expf(s_acc[nt][0] - mn0);
            float p1 = __expf(s_acc[nt][1] - mn0);
            float p2 = __expf(s_acc[nt][2] - mn1);
            float p3 = __expf(s_acc[nt][3] - mn1);
            s_acc[nt][0] = p0; s_acc[nt][1] = p1;
            s_acc[nt][2] = p2; s_acc[nt][3] = p3;
            sum0 += p0 + p1; sum1 += p2 + p3;
        }
        sum0 += __shfl_xor_sync(0xffffffffu, sum0, 1);
        sum0 += __shfl_xor_sync(0xffffffffu, sum0, 2);
        sum1 += __shfl_xor_sync(0xffffffffu, sum1, 1);
        sum1 += __shfl_xor_sync(0xffffffffu, sum1, 2);
        l0 = l0 * al0 + sum0;
        l1 = l1 * al1 + sum1;

        #pragma unroll
        for (int nt = 0; nt < 8; nt++) {
            o[nt][0] *= al0; o[nt][1] *= al0;
            o[nt][2] *= al1; o[nt][3] *= al1;
        }

        // ---- O += P V (bf16x3; P frags from S accumulators)
        const uint32_t vb = kb + 2 * ATILE;
        #pragma unroll
        for (int ks = 0; ks < 4; ks++) {
            uint32_t ah[4], al[4];
            #pragma unroll
            for (int q = 0; q < 4; q++) {
                int nt = 2 * ks + (q >> 1);
                float vx = s_acc[nt][(q & 1) * 2];
                float vy = s_acc[nt][(q & 1) * 2 + 1];
                split2(vx, vy, ah[q], al[q]);
            }
            #pragma unroll
            for (int np = 0; np < 4; np++) {
                uint32_t va = vb + (ks * 16 + rowin + (mat & 1) * 8) * AROW
                              + (np * 16 + (mat >> 1) * 8) * 2;
                uint32_t vhf[4], vlf[4];
                ldsm_x4_t(vhf, va);
                ldsm_x4_t(vlf, va + ATILE);
                #pragma unroll
                for (int h2 = 0; h2 < 2; h2++) {
                    int nt = np * 2 + h2;
                    mma16816(o[nt], ah, vhf[2 * h2], vhf[2 * h2 + 1]);
                    mma16816(o[nt], ah, vlf[2 * h2], vlf[2 * h2 + 1]);
                    mma16816(o[nt], al, vhf[2 * h2], vhf[2 * h2 + 1]);
                }
            }
        }
        __syncthreads();
    }

    // ---- epilogue: normalize, split, scatter to out-proj A operand
    float inv0 = 1.0f / l0, inv1 = 1.0f / l1;
    int y0 = tg0, y1 = tg0 + 8;
    #pragma unroll
    for (int nt = 0; nt < 8; nt++) {
        int col = hx * 64 + nt * 8 + tig * 2;
        uint32_t hi, lo;
        split2(o[nt][0] * inv0, o[nt][1] * inv0, hi, lo);
        size_t i0 = (size_t)(y0 * BZ + bx) * E_ + col;
        *reinterpret_cast<uint32_t*>(&g_Ahi[i0]) = hi;
        *reinterpret_cast<uint32_t*>(&g_Alo[i0]) = lo;
        split2(o[nt][2] * inv1, o[nt][3] * inv1, hi, lo);
        size_t i1 = (size_t)(y1 * BZ + bx) * E_ + col;
        *reinterpret_cast<uint32_t*>(&g_Ahi[i1]) = hi;
        *reinterpret_cast<uint32_t*>(&g_Alo[i1]) = lo;
    }
}

// ---------------------------------------------------------------- host side
extern "C" void kernel_launch(void* const* d_in, const int* in_sizes, int n_in,
                              void* d_out, int out_size)
{
    (void)in_sizes; (void)n_in; (void)out_size;
    const float* query   = (const float*)d_in[0];
    const float* q_w     = (const float*)d_in[1];
    const float* q_b     = (const float*)d_in[2];
    const float* k_w     = (const float*)d_in[3];
    const float* k_b     = (const float*)d_in[4];
    const float* v_w     = (const float*)d_in[5];
    const float* v_b     = (const float*)d_in[6];
    const float* out_w   = (const float*)d_in[7];
    const float* out_b   = (const float*)d_in[8];
    const float* rel_emb = (const float*)d_in[9];
    const float* grep_w  = (const float*)d_in[10];
    const float* grep_b  = (const float*)d_in[11];
    const float* grep_a  = (const float*)d_in[12];
    const float* bias_k  = (const float*)d_in[13];
    const float* bias_v  = (const float*)d_in[14];
    float* out = (float*)d_out;

    void *pAhi, *pAlo, *pWhi, *pWlo;
    cudaGetSymbolAddress(&pAhi, g_Ahi);
    cudaGetSymbolAddress(&pAlo, g_Alo);
    cudaGetSymbolAddress(&pWhi, g_Whi);
    cudaGetSymbolAddress(&pWlo, g_Wlo);

    __nv_bfloat16* Ahi = (__nv_bfloat16*)pAhi;
    __nv_bfloat16* Alo = (__nv_bfloat16*)pAlo;
    const size_t wsz = (size_t)E_ * E_;
    __nv_bfloat16* Whi = (__nv_bfloat16*)pWhi;
    __nv_bfloat16* Wlo = (__nv_bfloat16*)pWlo;

    cudaFuncSetAttribute((const void*)mma_gemm<0>,
        cudaFuncAttributeMaxDynamicSharedMemorySize, GEMM_SMEM);
    cudaFuncSetAttribute((const void*)mma_gemm<1>,
        cudaFuncAttributeMaxDynamicSharedMemorySize, GEMM_SMEM);
    cudaFuncSetAttribute((const void*)mma_gemm<2>,
        cudaFuncAttributeMaxDynamicSharedMemorySize, GEMM_SMEM);
    cudaFuncSetAttribute((const void*)mma_gemm<3>,
        cudaFuncAttributeMaxDynamicSharedMemorySize, GEMM_SMEM);
    cudaFuncSetAttribute((const void*)attn_mma,
        cudaFuncAttributeMaxDynamicSharedMemorySize, ATTN_SMEM);

    dim3 tgrid(32, 32), tblock(32, 8);
    dim3 ggrid(E_ / 128, M_ / 128);    // (8, 32)

    split_kernel<<<4096, 256>>>(query, Ahi, Alo, M_ * E_ / 4);
    transW_kernel<<<tgrid, tblock>>>(q_w,   Whi + 0 * wsz, Wlo + 0 * wsz);
    transW_kernel<<<tgrid, tblock>>>(k_w,   Whi + 1 * wsz, Wlo + 1 * wsz);
    transW_kernel<<<tgrid, tblock>>>(v_w,   Whi + 2 * wsz, Wlo + 2 * wsz);
    transW_kernel<<<tgrid, tblock>>>(out_w, Whi + 3 * wsz, Wlo + 3 * wsz);

    mma_gemm<0><<<ggrid, 256, GEMM_SMEM>>>(Ahi, Alo, Whi + 0 * wsz, Wlo + 0 * wsz, q_b, nullptr);
    mma_gemm<1><<<ggrid, 256, GEMM_SMEM>>>(Ahi, Alo, Whi + 1 * wsz, Wlo + 1 * wsz, k_b, nullptr);
    mma_gemm<2><<<ggrid, 256, GEMM_SMEM>>>(Ahi, Alo, Whi + 2 * wsz, Wlo + 2 * wsz, v_b, nullptr);

    biaskv_kernel<<<16, 256>>>(bias_k, bias_v);
    pb_kernel<<<8, 256>>>(rel_emb);
    gate_kernel<<<8192, 256>>>(grep_w, grep_b, grep_a);

    attn_mma<<<dim3(16, 64), 128, ATTN_SMEM>>>();

    mma_gemm<3><<<ggrid, 256, GEMM_SMEM>>>(Ahi, Alo, Whi + 3 * wsz, Wlo + 3 * wsz, out_b, out);
}

// round 5
// speedup vs baseline: 2.8738x; 1.0987x over previous
#include <cuda_runtime.h>
#include <cuda_bf16.h>
#include <cstdint>

// ---------------------------------------------------------------- constants
#define T_   1024
#define BZ   4
#define E_   1024
#define NH   16
#define HD   64
#define BH   64          // bsz * nh
#define SLEN 1025        // src_len = T + 1 (bias_kv)
#define M_   4096        // T*B rows of the projection GEMMs
#define QSCALE 0.00390625f   // hd^-0.5 / ALPHA = (1/8)/32 = 1/256

// GEMM tiling (mma.sync path)
#define BKB   64         // bytes of K per iter (32 bf16)
#define ROWB  80         // padded smem row bytes (64B data + 16B pad)
#define TILEB (128 * ROWB)        // 10240 B per tile
#define STAGEB (4 * TILEB)        // Ahi Alo Bhi Blo = 40960 B
#define GEMM_SMEM (2 * STAGEB)    // 81920 B

// attention smem
#define AROW  144                 // 128B data + 16B pad
#define ATILE (64 * AROW)         // 9216 B
#define A_QH  0
#define A_QL  ATILE
#define A_ST  (2 * ATILE)         // stage base
#define A_STB (4 * ATILE)         // KH KL VH VL per stage
#define ATTN_SMEM (A_ST + 2 * A_STB)   // 92160 B

#define KVSZ ((size_t)BH * SLEN * HD + 8192)   // slack for chunk-16 overread

// ---------------------------------------------------------------- scratch
__device__ float g_Qf[(size_t)BH * T_ * HD];          // f32 Q (gate input)
__device__ __nv_bfloat16 g_Qh[(size_t)BH * T_ * HD];
__device__ __nv_bfloat16 g_Ql[(size_t)BH * T_ * HD];
__device__ __nv_bfloat16 g_Kh[KVSZ], g_Kl[KVSZ];
__device__ __nv_bfloat16 g_Vh[KVSZ], g_Vl[KVSZ];
__device__ float g_gate[(size_t)BH * T_];
__device__ float g_pb[(size_t)NH * 2048];

__device__ __nv_bfloat16 g_Ahi[(size_t)M_ * E_];   // GEMM A (query, then O)
__device__ __nv_bfloat16 g_Alo[(size_t)M_ * E_];
__device__ __nv_bfloat16 g_Whi[4][(size_t)E_ * E_];  // q,k,v contiguous + out
__device__ __nv_bfloat16 g_Wlo[4][(size_t)E_ * E_];

// ---------------------------------------------------------------- helpers
__device__ __forceinline__ uint32_t cvta_smem(const void* p) {
    uint32_t a;
    asm("{ .reg .u64 t; cvta.to.shared.u64 t, %1; cvt.u32.u64 %0, t; }"
        : "=r"(a) : "l"(p));
    return a;
}

#define CP16(dst, src) \
    asm volatile("cp.async.cg.shared.global [%0], [%1], 16;" \
        :: "r"(dst), "l"(src) : "memory")
#define CPCOMMIT() asm volatile("cp.async.commit_group;" ::: "memory")
#define CPWAIT1()  asm volatile("cp.async.wait_group 1;" ::: "memory")
#define CPWAIT0()  asm volatile("cp.async.wait_group 0;" ::: "memory")

__device__ __forceinline__ void ldsm_x4(uint32_t r[4], uint32_t addr) {
    asm volatile(
        "ldmatrix.sync.aligned.m8n8.x4.shared.b16 {%0,%1,%2,%3}, [%4];"
        : "=r"(r[0]), "=r"(r[1]), "=r"(r[2]), "=r"(r[3]) : "r"(addr));
}
__device__ __forceinline__ void ldsm_x4_t(uint32_t r[4], uint32_t addr) {
    asm volatile(
        "ldmatrix.sync.aligned.m8n8.x4.trans.shared.b16 {%0,%1,%2,%3}, [%4];"
        : "=r"(r[0]), "=r"(r[1]), "=r"(r[2]), "=r"(r[3]) : "r"(addr));
}

__device__ __forceinline__ void mma16816(float c[4], const uint32_t a[4],
                                         uint32_t b0, uint32_t b1) {
    asm volatile(
        "mma.sync.aligned.m16n8k16.row.col.f32.bf16.bf16.f32 "
        "{%0,%1,%2,%3}, {%4,%5,%6,%7}, {%8,%9}, {%0,%1,%2,%3};"
        : "+f"(c[0]), "+f"(c[1]), "+f"(c[2]), "+f"(c[3])
        : "r"(a[0]), "r"(a[1]), "r"(a[2]), "r"(a[3]), "r"(b0), "r"(b1));
}

__device__ __forceinline__ uint32_t packbf(__nv_bfloat16 a, __nv_bfloat16 b) {
    __nv_bfloat162 t(a, b);
    return *reinterpret_cast<uint32_t*>(&t);
}

__device__ __forceinline__ void split2(float x, float y,
                                       uint32_t& hi, uint32_t& lo) {
    __nv_bfloat16 hx = __float2bfloat16(x);
    __nv_bfloat16 hy = __float2bfloat16(y);
    __nv_bfloat16 lx = __float2bfloat16(x - __bfloat162float(hx));
    __nv_bfloat16 ly = __float2bfloat16(y - __bfloat162float(hy));
    hi = packbf(hx, hy);
    lo = packbf(lx, ly);
}

// ---------------------------------------------------------------- bf16 split
__global__ __launch_bounds__(256)
void split_kernel(const float* __restrict__ src,
                  __nv_bfloat16* __restrict__ hi,
                  __nv_bfloat16* __restrict__ lo, int n4)
{
    int i = blockIdx.x * blockDim.x + threadIdx.x;
    if (i >= n4) return;
    float4 v = reinterpret_cast<const float4*>(src)[i];
    uint32_t h0, l0, h1, l1;
    split2(v.x, v.y, h0, l0);
    split2(v.z, v.w, h1, l1);
    uint32_t* hp = reinterpret_cast<uint32_t*>(hi);
    uint32_t* lp = reinterpret_cast<uint32_t*>(lo);
    hp[2 * i] = h0; hp[2 * i + 1] = h1;
    lp[2 * i] = l0; lp[2 * i + 1] = l1;
}

// transpose + split all 4 weights (z = which matrix)
__global__ __launch_bounds__(256)
void transW_all(const float* __restrict__ w0, const float* __restrict__ w1,
                const float* __restrict__ w2, const float* __restrict__ w3)
{
    __shared__ float tile[32][33];
    int tx = threadIdx.x, ty = threadIdx.y;          // 32 x 8
    int bx = blockIdx.x * 32, by = blockIdx.y * 32;
    int z = blockIdx.z;
    const float* W = (z == 0) ? w0 : (z == 1) ? w1 : (z == 2) ? w2 : w3;
    __nv_bfloat16* hi = g_Whi[z];
    __nv_bfloat16* lo = g_Wlo[z];
    #pragma unroll
    for (int r = 0; r < 4; r++)
        tile[ty + r * 8][tx] = W[(size_t)(by + ty + r * 8) * E_ + bx + tx];
    __syncthreads();
    #pragma unroll
    for (int r = 0; r < 4; r++) {
        int n = bx + ty + r * 8, k = by + tx;
        float v = tile[tx][ty + r * 8];
        __nv_bfloat16 h = __float2bfloat16(v);
        hi[(size_t)n * E_ + k] = h;
        lo[(size_t)n * E_ + k] = __float2bfloat16(v - __bfloat162float(h));
    }
}

// ---------------------------------------------------------------- mma GEMM
// MODE 4: fused QKV projection. B = g_Whi[0..2] viewed as [3072][1024].
//         bn 0-7 -> Q (scale + scatter + f32), 8-15 -> K, 16-23 -> V.
// MODE 3: out proj -> Cout f32 row-major.
template<int MODE>
__global__ __launch_bounds__(256)
void mma_gemm(const __nv_bfloat16* __restrict__ Ahi,
              const __nv_bfloat16* __restrict__ Alo,
              const __nv_bfloat16* __restrict__ Bhi,
              const __nv_bfloat16* __restrict__ Blo,
              const float* __restrict__ bias0,
              const float* __restrict__ bias1,
              const float* __restrict__ bias2,
              float* __restrict__ Cout)
{
    extern __shared__ __align__(16) char sm_[];
    const int tid = threadIdx.x, lane = tid & 31, w = tid >> 5;
    const int bn = blockIdx.x, bm = blockIdx.y;
    const uint32_t smem_u = cvta_smem(sm_);

    const __nv_bfloat16* gsrc0 = Ahi + (size_t)(bm * 128) * 1024;
    const __nv_bfloat16* gsrc1 = Alo + (size_t)(bm * 128) * 1024;
    const __nv_bfloat16* gsrc2 = Bhi + (size_t)(bn * 128) * 1024;
    const __nv_bfloat16* gsrc3 = Blo + (size_t)(bn * 128) * 1024;

    const int row0 = tid >> 2, ch0 = tid & 3;
    const int row1 = (tid + 256) >> 2;

    auto load_stage = [&](int it, int s) {
        uint32_t sb = smem_u + s * STAGEB;
        const int kb = it * BKB;
        const char* g0 = (const char*)gsrc0 + kb;
        const char* g1 = (const char*)gsrc1 + kb;
        const char* g2 = (const char*)gsrc2 + kb;
        const char* g3 = (const char*)gsrc3 + kb;
        uint32_t d0 = sb + row0 * ROWB + ch0 * 16;
        uint32_t d1 = sb + row1 * ROWB + ch0 * 16;
        size_t o0 = (size_t)row0 * 2048 + ch0 * 16;
        size_t o1 = (size_t)row1 * 2048 + ch0 * 16;
        CP16(d0,              g0 + o0); CP16(d1,              g0 + o1);
        CP16(d0 + TILEB,      g1 + o0); CP16(d1 + TILEB,      g1 + o1);
        CP16(d0 + 2 * TILEB,  g2 + o0); CP16(d1 + 2 * TILEB,  g2 + o1);
        CP16(d0 + 3 * TILEB,  g3 + o0); CP16(d1 + 3 * TILEB,  g3 + o1);
        CPCOMMIT();
    };

    float acc[2][8][4] = {};
    const int wm = w & 3, wn = w >> 2;
    const int m0 = wm * 32, n0 = wn * 64;
    const int gid = lane >> 2, tig = lane & 3;
    const int mat = lane >> 3, rowin = lane & 7;

    const int a_row = rowin + (mat & 1) * 8;
    const int a_kof = (mat >> 1) * 16;
    const int b_row = rowin + (mat >> 1) * 8;
    const int b_kof = (mat & 1) * 16;

    load_stage(0, 0);

    for (int it = 0; it < 32; it++) {
        int s = it & 1;
        if (it + 1 < 32) { load_stage(it + 1, s ^ 1); CPWAIT1(); }
        else             { CPWAIT0(); }
        __syncthreads();
        uint32_t sb = smem_u + s * STAGEB;
        #pragma unroll
        for (int ks = 0; ks < 2; ks++) {
            uint32_t ahi[2][4], alo[2][4];
            #pragma unroll
            for (int mt = 0; mt < 2; mt++) {
                uint32_t ar = sb + (m0 + mt * 16 + a_row) * ROWB
                              + ks * 32 + a_kof;
                ldsm_x4(ahi[mt], ar);
                ldsm_x4(alo[mt], ar + TILEB);
            }
            #pragma unroll
            for (int np = 0; np < 4; np++) {
                uint32_t br = sb + 2 * TILEB
                              + (n0 + np * 16 + b_row) * ROWB
                              + ks * 32 + b_kof;
                uint32_t bhi[4], blo[4];
                ldsm_x4(bhi, br);
                ldsm_x4(blo, br + TILEB);
                #pragma unroll
                for (int h = 0; h < 2; h++) {
                    int nt = np * 2 + h;
                    #pragma unroll
                    for (int mt = 0; mt < 2; mt++) {
                        mma16816(acc[mt][nt], ahi[mt], bhi[2 * h], bhi[2 * h + 1]);
                        mma16816(acc[mt][nt], ahi[mt], blo[2 * h], blo[2 * h + 1]);
                        mma16816(acc[mt][nt], alo[mt], bhi[2 * h], bhi[2 * h + 1]);
                    }
                }
            }
        }
        __syncthreads();
    }

    // ---- epilogue
    const int sel = (MODE == 4) ? (bn >> 3) : 3;           // 0=Q 1=K 2=V
    const float* bias = (MODE == 3) ? bias0
                        : (sel == 0) ? bias0 : (sel == 1) ? bias1 : bias2;
    #pragma unroll
    for (int mt = 0; mt < 2; mt++) {
        #pragma unroll
        for (int nt = 0; nt < 8; nt++) {
            // n within the (sub-)matrix
            int n = (MODE == 4 ? (bn & 7) : bn) * 128 + n0 + nt * 8 + tig * 2;
            float bx = bias[n], by = bias[n + 1];
            #pragma unroll
            for (int half = 0; half < 2; half++) {
                int m = bm * 128 + m0 + mt * 16 + gid + half * 8;
                float vx = acc[mt][nt][half * 2 + 0] + bx;
                float vy = acc[mt][nt][half * 2 + 1] + by;
                if (MODE == 3) {
                    *reinterpret_cast<float2*>(&Cout[(size_t)m * E_ + n]) =
                        make_float2(vx, vy);
                } else {
                    int t = m >> 2, b = m & 3;
                    int h = n >> 6, d = n & 63;
                    size_t idx;
                    if (sel == 0) {
                        int x = b * 16 + (t >> 6);
                        int y = ((t & 63) << 4) | h;
                        idx = ((size_t)x * T_ + y) * HD + d;
                        vx *= QSCALE; vy *= QSCALE;
                        *reinterpret_cast<float2*>(&g_Qf[idx]) =
                            make_float2(vx, vy);
                    } else {
                        int u = t * 16 + h;
                        int x = b * 16 + u / 1025;
                        int y = u % 1025;
                        idx = ((size_t)x * SLEN + y) * HD + d;
                    }
                    uint32_t hi, lo;
                    split2(vx, vy, hi, lo);
                    __nv_bfloat16* ph = (sel == 0) ? g_Qh : (sel == 1) ? g_Kh : g_Vh;
                    __nv_bfloat16* pl = (sel == 0) ? g_Ql : (sel == 1) ? g_Kl : g_Vl;
                    *reinterpret_cast<uint32_t*>(&ph[idx]) = hi;
                    *reinterpret_cast<uint32_t*>(&pl[idx]) = lo;
                }
            }
        }
    }
}

// ---------------------------------------------------------------- small kernels
__global__ void biaskv_kernel(const float* __restrict__ bias_k,
                              const float* __restrict__ bias_v)
{
    int i = blockIdx.x * blockDim.x + threadIdx.x;
    if (i >= BZ * NH * HD) return;
    int b = i >> 10, h = (i >> 6) & 15, d = i & 63;
    int x = b * 16 + 15;
    int y = 1009 + h;
    size_t idx = ((size_t)x * SLEN + y) * HD + d;
    float kv = bias_k[h * HD + d];
    float vv = bias_v[h * HD + d];
    __nv_bfloat16 kh = __float2bfloat16(kv);
    __nv_bfloat16 vh = __float2bfloat16(vv);
    g_Kh[idx] = kh; g_Kl[idx] = __float2bfloat16(kv - __bfloat162float(kh));
    g_Vh[idx] = vh; g_Vl[idx] = __float2bfloat16(vv - __bfloat162float(vh));
}

__global__ void pb_kernel(const float* __restrict__ rel_emb)
{
    int d = blockIdx.x * blockDim.x + threadIdx.x;
    if (d >= 2048) return;
    int rel = d - 1023;
    int bkt = rel > 0 ? 16 : 0;
    int a = rel < 0 ? -rel : rel;
    int bu;
    if (a < 8) {
        bu = a;
    } else {
        float lf = logf((float)a * 0.125f + 1e-6f) * (8.0f / 2.772588722239781f);
        int large = 8 + (int)lf;
        bu = large < 15 ? large : 15;
    }
    int bucket = bkt + bu;
    #pragma unroll
    for (int h = 0; h < NH; h++)
        g_pb[h * 2048 + d] = rel_emb[bucket * NH + h];
}

__global__ __launch_bounds__(256)
void gate_kernel(const float* __restrict__ grep_w,
                 const float* __restrict__ grep_b,
                 const float* __restrict__ grep_a)
{
    __shared__ float gws[64];
    __shared__ float gbs;
    int tid = threadIdx.x;
    if (tid < 64) {
        float s = 0.f;
        #pragma unroll
        for (int j = 0; j < 8; j++) s += grep_w[tid * 8 + j];
        gws[tid] = s;
    }
    if (tid == 64) {
        float s = 0.f;
        #pragma unroll
        for (int j = 0; j < 8; j++) s += grep_b[j];
        gbs = s;
    }
    __syncthreads();
    int warp = tid >> 5, lane = tid & 31;
    int row = blockIdx.x * 8 + warp;
    if (row < BH * T_) {
        const float* q = &g_Qf[(size_t)row * HD];
        float s = q[lane] * gws[lane] + q[lane + 32] * gws[lane + 32];
        #pragma unroll
        for (int off = 16; off; off >>= 1)
            s += __shfl_xor_sync(0xffffffffu, s, off);
        if (lane == 0) {
            int hx = (row >> 10) & 15;
            float val = s * 256.0f + gbs;
            float sig = 1.0f / (1.0f + __expf(-val));
            g_gate[row] = sig * grep_a[hx];
        }
    }
}

// ---------------------------------------------------------------- attention (mma)
__global__ __launch_bounds__(128)
void attn_mma()
{
    extern __shared__ __align__(16) char asmm[];
    const uint32_t smem_u = cvta_smem(asmm);
    const int tid = threadIdx.x, lane = tid & 31, w = tid >> 5;
    const int gid = lane >> 2, tig = lane & 3;
    const int mat = lane >> 3, rowin = lane & 7;
    const int x = blockIdx.y, t0 = blockIdx.x * 64;
    const int hx = x & 15, bx = x >> 4;

    {
        const char* srcH = (const char*)g_Qh + ((size_t)x * T_ + t0) * HD * 2;
        const char* srcL = (const char*)g_Ql + ((size_t)x * T_ + t0) * HD * 2;
        #pragma unroll
        for (int i = 0; i < 8; i++) {
            int idx = tid + i * 128;
            int tile = idx >> 9, row = (idx >> 3) & 63, c = idx & 7;
            const char* s = (tile ? srcL : srcH) + (size_t)row * 128 + c * 16;
            uint32_t d = smem_u + (tile ? A_QL : A_QH) + row * AROW + c * 16;
            CP16(d, s);
        }
        CPCOMMIT();
    }

    const char* pKh = (const char*)g_Kh + (size_t)x * SLEN * HD * 2;
    const char* pKl = (const char*)g_Kl + (size_t)x * SLEN * HD * 2;
    const char* pVh = (const char*)g_Vh + (size_t)x * SLEN * HD * 2;
    const char* pVl = (const char*)g_Vl + (size_t)x * SLEN * HD * 2;

    auto load_kv = [&](int ch, int buf) {
        int s0 = ch * 64;
        #pragma unroll
        for (int i = 0; i < 16; i++) {
            int idx = tid + i * 128;
            int tile = idx >> 9, row = (idx >> 3) & 63, c = idx & 7;
            const char* p = (tile & 2) ? ((tile & 1) ? pVl : pVh)
                                       : ((tile & 1) ? pKl : pKh);
            uint32_t d = smem_u + A_ST + buf * A_STB + tile * ATILE
                         + row * AROW + c * 16;
            CP16(d, p + ((size_t)(s0 + row)) * 128 + c * 16);
        }
        CPCOMMIT();
    };

    load_kv(0, 0);

    float m0 = -1e30f, m1 = -1e30f, l0 = 0.f, l1 = 0.f;
    float o[8][4] = {};
    uint32_t qh[4][4], ql[4][4];
    const int tg0 = t0 + w * 16 + gid;
    const float gate0 = g_gate[(size_t)x * T_ + tg0];
    const float gate1 = g_gate[(size_t)x * T_ + tg0 + 8];

    for (int ch = 0; ch < 17; ch++) {
        int buf = ch & 1;
        if (ch + 1 < 17) { load_kv(ch + 1, buf ^ 1); CPWAIT1(); }
        else             { CPWAIT0(); }
        __syncthreads();

        if (ch == 0) {
            #pragma unroll
            for (int ks = 0; ks < 4; ks++) {
                uint32_t qa = smem_u + A_QH
                    + (w * 16 + rowin + (mat & 1) * 8) * AROW
                    + ks * 32 + (mat >> 1) * 16;
                ldsm_x4(qh[ks], qa);
                ldsm_x4(ql[ks], qa + ATILE);
            }
        }

        const uint32_t kb = smem_u + A_ST + buf * A_STB;

        float s_acc[8][4] = {};
        #pragma unroll
        for (int ks = 0; ks < 4; ks++) {
            #pragma unroll
            for (int np = 0; np < 4; np++) {
                uint32_t ka = kb + (np * 16 + rowin + (mat >> 1) * 8) * AROW
                              + ks * 32 + (mat & 1) * 16;
                uint32_t khf[4], klf[4];
                ldsm_x4(khf, ka);
                ldsm_x4(klf, ka + ATILE);
                #pragma unroll
                for (int h2 = 0; h2 < 2; h2++) {
                    int nt = np * 2 + h2;
                    mma16816(s_acc[nt], qh[ks], khf[2 * h2], khf[2 * h2 + 1]);
                    mma16816(s_acc[nt], qh[ks], klf[2 * h2], klf[2 * h2 + 1]);
                    mma16816(s_acc[nt], ql[ks], khf[2 * h2], khf[2 * h2 + 1]);
                }
            }
        }

        int s0 = ch * 64;
        #pragma unroll
        for (int nt = 0; nt < 8; nt++) {
            #pragma unroll
            for (int j = 0; j < 4; j++) {
                int sg = s0 + nt * 8 + tig * 2 + (j & 1);
                int tg = tg0 + (j >> 1) * 8;
                float g = (j >> 1) ? gate1 : gate0;
                if (sg < SLEN)
                    s_acc[nt][j] += g * __ldg(&g_pb[hx * 2048 + sg - tg + 1023]);
                else
                    s_acc[nt][j] = -1e30f;
            }
        }

        float mx0 = -1e30f, mx1 = -1e30f;
        #pragma unroll
        for (int nt = 0; nt < 8; nt++) {
            mx0 = fmaxf(mx0, fmaxf(s_acc[nt][0], s_acc[nt][1]));
            mx1 = fmaxf(mx1, fmaxf(s_acc[nt][2], s_acc[nt][3]));
        }
        mx0 = fmaxf(mx0, __shfl_xor_sync(0xffffffffu, mx0, 1));
        mx0 = fmaxf(mx0, __shfl_xor_sync(0xffffffffu, mx0, 2));
        mx1 = fmaxf(mx1, __shfl_xor_sync(0xffffffffu, mx1, 1));
        mx1 = fmaxf(mx1, __shfl_xor_sync(0xffffffffu, mx1, 2));
        float mn0 = fmaxf(m0, mx0), mn1 = fmaxf(m1, mx1);
        float al0 = __expf(m0 - mn0), al1 = __expf(m1 - mn1);
        m0 = mn0; m1 = mn1;

        float sum0 = 0.f, sum1 = 0.f;
        #pragma unroll
        for (int nt = 0; nt < 8; nt++) {
            float p0 = __expf(s_acc[nt][0] - mn0);
            float p1 = __expf(s_acc[nt][1] - mn0);
            float p2 = __expf(s_acc[nt][2] - mn1);
            float p3 = __expf(s_acc[nt][3] - mn1);
            s_acc[nt][0] = p0; s_acc[nt][1] = p1;
            s_acc[nt][2] = p2; s_acc[nt][3] = p3;
            sum0 += p0 + p1; sum1 += p2 + p3;
        }
        sum0 += __shfl_xor_sync(0xffffffffu, sum0, 1);
        sum0 += __shfl_xor_sync(0xffffffffu, sum0, 2);
        sum1 += __shfl_xor_sync(0xffffffffu, sum1, 1);
        sum1 += __shfl_xor_sync(0xffffffffu, sum1, 2);
        l0 = l0 * al0 + sum0;
        l1 = l1 * al1 + sum1;

        #pragma unroll
        for (int nt = 0; nt < 8; nt++) {
            o[nt][0] *= al0; o[nt][1] *= al0;
            o[nt][2] *= al1; o[nt][3] *= al1;
        }

        const uint32_t vb = kb + 2 * ATILE;
        #pragma unroll
        for (int ks = 0; ks < 4; ks++) {
            uint32_t ah[4], al[4];
            #pragma unroll
            for (int q = 0; q < 4; q++) {
                int nt = 2 * ks + (q >> 1);
                float vx = s_acc[nt][(q & 1) * 2];
                float vy = s_acc[nt][(q & 1) * 2 + 1];
                split2(vx, vy, ah[q], al[q]);
            }
            #pragma unroll
            for (int np = 0; np < 4; np++) {
                uint32_t va = vb + (ks * 16 + rowin + (mat & 1) * 8) * AROW
                              + (np * 16 + (mat >> 1) * 8) * 2;
                uint32_t vhf[4], vlf[4];
                ldsm_x4_t(vhf, va);
                ldsm_x4_t(vlf, va + ATILE);
                #pragma unroll
                for (int h2 = 0; h2 < 2; h2++) {
                    int nt = np * 2 + h2;
                    mma16816(o[nt], ah, vhf[2 * h2], vhf[2 * h2 + 1]);
                    mma16816(o[nt], ah, vlf[2 * h2], vlf[2 * h2 + 1]);
                    mma16816(o[nt], al, vhf[2 * h2], vhf[2 * h2 + 1]);
                }
            }
        }
        __syncthreads();
    }

    float inv0 = 1.0f / l0, inv1 = 1.0f / l1;
    int y0 = tg0, y1 = tg0 + 8;
    #pragma unroll
    for (int nt = 0; nt < 8; nt++) {
        int col = hx * 64 + nt * 8 + tig * 2;
        uint32_t hi, lo;
        split2(o[nt][0] * inv0, o[nt][1] * inv0, hi, lo);
        size_t i0 = (size_t)(y0 * BZ + bx) * E_ + col;
        *reinterpret_cast<uint32_t*>(&g_Ahi[i0]) = hi;
        *reinterpret_cast<uint32_t*>(&g_Alo[i0]) = lo;
        split2(o[nt][2] * inv1, o[nt][3] * inv1, hi, lo);
        size_t i1 = (size_t)(y1 * BZ + bx) * E_ + col;
        *reinterpret_cast<uint32_t*>(&g_Ahi[i1]) = hi;
        *reinterpret_cast<uint32_t*>(&g_Alo[i1]) = lo;
    }
}

// ---------------------------------------------------------------- host side
extern "C" void kernel_launch(void* const* d_in, const int* in_sizes, int n_in,
                              void* d_out, int out_size)
{
    (void)in_sizes; (void)n_in; (void)out_size;
    const float* query   = (const float*)d_in[0];
    const float* q_w     = (const float*)d_in[1];
    const float* q_b     = (const float*)d_in[2];
    const float* k_w     = (const float*)d_in[3];
    const float* k_b     = (const float*)d_in[4];
    const float* v_w     = (const float*)d_in[5];
    const float* v_b     = (const float*)d_in[6];
    const float* out_w   = (const float*)d_in[7];
    const float* out_b   = (const float*)d_in[8];
    const float* rel_emb = (const float*)d_in[9];
    const float* grep_w  = (const float*)d_in[10];
    const float* grep_b  = (const float*)d_in[11];
    const float* grep_a  = (const float*)d_in[12];
    const float* bias_k  = (const float*)d_in[13];
    const float* bias_v  = (const float*)d_in[14];
    float* out = (float*)d_out;

    void *pAhi, *pAlo, *pWhi, *pWlo;
    cudaGetSymbolAddress(&pAhi, g_Ahi);
    cudaGetSymbolAddress(&pAlo, g_Alo);
    cudaGetSymbolAddress(&pWhi, g_Whi);
    cudaGetSymbolAddress(&pWlo, g_Wlo);

    __nv_bfloat16* Ahi = (__nv_bfloat16*)pAhi;
    __nv_bfloat16* Alo = (__nv_bfloat16*)pAlo;
    const size_t wsz = (size_t)E_ * E_;
    __nv_bfloat16* Whi = (__nv_bfloat16*)pWhi;
    __nv_bfloat16* Wlo = (__nv_bfloat16*)pWlo;

    cudaFuncSetAttribute((const void*)mma_gemm<3>,
        cudaFuncAttributeMaxDynamicSharedMemorySize, GEMM_SMEM);
    cudaFuncSetAttribute((const void*)mma_gemm<4>,
        cudaFuncAttributeMaxDynamicSharedMemorySize, GEMM_SMEM);
    cudaFuncSetAttribute((const void*)attn_mma,
        cudaFuncAttributeMaxDynamicSharedMemorySize, ATTN_SMEM);

    // launch order keeps the QKV GEMM at slot #4 (ncu capture position)
    split_kernel<<<4096, 256>>>(query, Ahi, Alo, M_ * E_ / 4);          // 1
    transW_all<<<dim3(32, 32, 4), dim3(32, 8)>>>(q_w, k_w, v_w, out_w); // 2
    biaskv_kernel<<<16, 256>>>(bias_k, bias_v);                         // 3
    mma_gemm<4><<<dim3(24, 32), 256, GEMM_SMEM>>>(                      // 4
        Ahi, Alo, Whi, Wlo, q_b, k_b, v_b, nullptr);
    pb_kernel<<<8, 256>>>(rel_emb);                                     // 5
    gate_kernel<<<8192, 256>>>(grep_w, grep_b, grep_a);                 // 6
    attn_mma<<<dim3(16, 64), 128, ATTN_SMEM>>>();                       // 7
    mma_gemm<3><<<dim3(8, 32), 256, GEMM_SMEM>>>(                       // 8
        Ahi, Alo, Whi + 3 * wsz, Wlo + 3 * wsz, out_b, nullptr, nullptr, out);
}

// round 6
// speedup vs baseline: 3.0920x; 1.0759x over previous
#include <cuda_runtime.h>
#include <cuda_bf16.h>
#include <cstdint>

// ---------------------------------------------------------------- constants
#define T_   1024
#define BZ   4
#define E_   1024
#define NH   16
#define HD   64
#define BH   64          // bsz * nh
#define SLEN 1025        // src_len = T + 1 (bias_kv)
#define M_   4096        // T*B rows of the projection GEMMs
#define QSCALE 0.00390625f   // hd^-0.5 / ALPHA = (1/8)/32 = 1/256

// GEMM tiling: CTA 256x128, 8 warps (4x2), warp 64x64, K-chunk 32 bf16
#define GROWB 80                   // padded smem row bytes
#define SA_SZ (256 * GROWB)        // 20480 (one A tile: hi or lo)
#define SB_SZ (128 * GROWB)        // 10240
#define SB_OFF (2 * SA_SZ)         // 40960
#define STAGE (2 * SA_SZ + 2 * SB_SZ)   // 61440
#define GEMM_SMEM (3 * STAGE)      // 184320

// attention smem
#define AROW  144                 // 128B data + 16B pad
#define ATILE (64 * AROW)         // 9216 B
#define A_QH  0
#define A_QL  ATILE
#define A_ST  (2 * ATILE)         // stage base
#define A_STB (4 * ATILE)         // KH KL VH VL per stage
#define ATTN_SMEM (A_ST + 2 * A_STB)   // 92160 B

#define KVSZ ((size_t)BH * SLEN * HD + 8192)

// ---------------------------------------------------------------- scratch
__device__ float g_Qf[(size_t)BH * T_ * HD];          // f32 Q (gate input)
__device__ __nv_bfloat16 g_Qh[(size_t)BH * T_ * HD];
__device__ __nv_bfloat16 g_Ql[(size_t)BH * T_ * HD];
__device__ __nv_bfloat16 g_Kh[KVSZ], g_Kl[KVSZ];
__device__ __nv_bfloat16 g_Vh[KVSZ], g_Vl[KVSZ];
__device__ float g_gate[(size_t)BH * T_];
__device__ float g_pb[(size_t)NH * 2048];

__device__ __nv_bfloat16 g_Ahi[(size_t)M_ * E_];   // GEMM A (query, then O)
__device__ __nv_bfloat16 g_Alo[(size_t)M_ * E_];
__device__ __nv_bfloat16 g_Whi[4][(size_t)E_ * E_];  // q,k,v contiguous + out
__device__ __nv_bfloat16 g_Wlo[4][(size_t)E_ * E_];

// ---------------------------------------------------------------- helpers
__device__ __forceinline__ uint32_t cvta_smem(const void* p) {
    uint32_t a;
    asm("{ .reg .u64 t; cvta.to.shared.u64 t, %1; cvt.u32.u64 %0, t; }"
        : "=r"(a) : "l"(p));
    return a;
}

#define CP16(dst, src) \
    asm volatile("cp.async.cg.shared.global [%0], [%1], 16;" \
        :: "r"(dst), "l"(src) : "memory")
#define CPCOMMIT() asm volatile("cp.async.commit_group;" ::: "memory")
#define CPWAIT1()  asm volatile("cp.async.wait_group 1;" ::: "memory")
#define CPWAIT0()  asm volatile("cp.async.wait_group 0;" ::: "memory")

__device__ __forceinline__ void ldsm_x4(uint32_t r[4], uint32_t addr) {
    asm volatile(
        "ldmatrix.sync.aligned.m8n8.x4.shared.b16 {%0,%1,%2,%3}, [%4];"
        : "=r"(r[0]), "=r"(r[1]), "=r"(r[2]), "=r"(r[3]) : "r"(addr));
}
__device__ __forceinline__ void ldsm_x4_t(uint32_t r[4], uint32_t addr) {
    asm volatile(
        "ldmatrix.sync.aligned.m8n8.x4.trans.shared.b16 {%0,%1,%2,%3}, [%4];"
        : "=r"(r[0]), "=r"(r[1]), "=r"(r[2]), "=r"(r[3]) : "r"(addr));
}

__device__ __forceinline__ void mma16816(float c[4], const uint32_t a[4],
                                         uint32_t b0, uint32_t b1) {
    asm volatile(
        "mma.sync.aligned.m16n8k16.row.col.f32.bf16.bf16.f32 "
        "{%0,%1,%2,%3}, {%4,%5,%6,%7}, {%8,%9}, {%0,%1,%2,%3};"
        : "+f"(c[0]), "+f"(c[1]), "+f"(c[2]), "+f"(c[3])
        : "r"(a[0]), "r"(a[1]), "r"(a[2]), "r"(a[3]), "r"(b0), "r"(b1));
}

__device__ __forceinline__ uint32_t packbf(__nv_bfloat16 a, __nv_bfloat16 b) {
    __nv_bfloat162 t(a, b);
    return *reinterpret_cast<uint32_t*>(&t);
}

__device__ __forceinline__ void split2(float x, float y,
                                       uint32_t& hi, uint32_t& lo) {
    __nv_bfloat16 hx = __float2bfloat16(x);
    __nv_bfloat16 hy = __float2bfloat16(y);
    __nv_bfloat16 lx = __float2bfloat16(x - __bfloat162float(hx));
    __nv_bfloat16 ly = __float2bfloat16(y - __bfloat162float(hy));
    hi = packbf(hx, hy);
    lo = packbf(lx, ly);
}

// ---------------------------------------------------------------- bf16 split
__global__ __launch_bounds__(256)
void split_kernel(const float* __restrict__ src,
                  __nv_bfloat16* __restrict__ hi,
                  __nv_bfloat16* __restrict__ lo, int n4)
{
    int i = blockIdx.x * blockDim.x + threadIdx.x;
    if (i >= n4) return;
    float4 v = reinterpret_cast<const float4*>(src)[i];
    uint32_t h0, l0, h1, l1;
    split2(v.x, v.y, h0, l0);
    split2(v.z, v.w, h1, l1);
    uint32_t* hp = reinterpret_cast<uint32_t*>(hi);
    uint32_t* lp = reinterpret_cast<uint32_t*>(lo);
    hp[2 * i] = h0; hp[2 * i + 1] = h1;
    lp[2 * i] = l0; lp[2 * i + 1] = l1;
}

// transpose + split all 4 weights (z = which matrix)
__global__ __launch_bounds__(256)
void transW_all(const float* __restrict__ w0, const float* __restrict__ w1,
                const float* __restrict__ w2, const float* __restrict__ w3)
{
    __shared__ float tile[32][33];
    int tx = threadIdx.x, ty = threadIdx.y;          // 32 x 8
    int bx = blockIdx.x * 32, by = blockIdx.y * 32;
    int z = blockIdx.z;
    const float* W = (z == 0) ? w0 : (z == 1) ? w1 : (z == 2) ? w2 : w3;
    __nv_bfloat16* hi = g_Whi[z];
    __nv_bfloat16* lo = g_Wlo[z];
    #pragma unroll
    for (int r = 0; r < 4; r++)
        tile[ty + r * 8][tx] = W[(size_t)(by + ty + r * 8) * E_ + bx + tx];
    __syncthreads();
    #pragma unroll
    for (int r = 0; r < 4; r++) {
        int n = bx + ty + r * 8, k = by + tx;
        float v = tile[tx][ty + r * 8];
        __nv_bfloat16 h = __float2bfloat16(v);
        hi[(size_t)n * E_ + k] = h;
        lo[(size_t)n * E_ + k] = __float2bfloat16(v - __bfloat162float(h));
    }
}

// ---------------------------------------------------------------- mma GEMM
// CTA tile 256x128, 8 warps (4x2), warp tile 64x64, 3-stage cp.async,
// one __syncthreads per K-iteration.
// MODE 4: fused QKV projection (B = [3072][1024]; bn/8 selects Q/K/V)
// MODE 3: out proj -> Cout f32 row-major
template<int MODE>
__global__ __launch_bounds__(256, 1)
void mma_gemm(const __nv_bfloat16* __restrict__ Ahi,
              const __nv_bfloat16* __restrict__ Alo,
              const __nv_bfloat16* __restrict__ Bhi,
              const __nv_bfloat16* __restrict__ Blo,
              const float* __restrict__ bias0,
              const float* __restrict__ bias1,
              const float* __restrict__ bias2,
              float* __restrict__ Cout)
{
    extern __shared__ __align__(16) char sm_[];
    const int tid = threadIdx.x, lane = tid & 31, w = tid >> 5;
    const int bn = blockIdx.x, bm = blockIdx.y;
    const uint32_t smem_u = cvta_smem(sm_);

    const char* gA0 = (const char*)(Ahi + (size_t)(bm * 256) * 1024);
    const char* gA1 = (const char*)(Alo + (size_t)(bm * 256) * 1024);
    const char* gB0 = (const char*)(Bhi + (size_t)(bn * 128) * 1024);
    const char* gB1 = (const char*)(Blo + (size_t)(bn * 128) * 1024);

    auto load_stage = [&](int it, int buf) {
        uint32_t sb = smem_u + buf * STAGE;
        const int kb = it * 64;
        #pragma unroll
        for (int i = 0; i < 12; i++) {
            int idx = tid + i * 256;
            if (idx < 2048) {
                int tile = idx >> 10, row = (idx >> 2) & 255, c = idx & 3;
                const char* g = (tile ? gA1 : gA0)
                                + (size_t)row * 2048 + kb + c * 16;
                CP16(sb + tile * SA_SZ + row * GROWB + c * 16, g);
            } else {
                int i2 = idx - 2048;
                int tile = i2 >> 9, row = (i2 >> 2) & 127, c = i2 & 3;
                const char* g = (tile ? gB1 : gB0)
                                + (size_t)row * 2048 + kb + c * 16;
                CP16(sb + SB_OFF + tile * SB_SZ + row * GROWB + c * 16, g);
            }
        }
        CPCOMMIT();
    };

    float acc[4][8][4] = {};
    const int wm = w >> 1, wn = w & 1;
    const int m0 = wm * 64, n0 = wn * 64;
    const int gid = lane >> 2, tig = lane & 3;
    const int mat = lane >> 3, rowin = lane & 7;

    const int a_row = rowin + (mat & 1) * 8;
    const int a_kof = (mat >> 1) * 16;
    const int b_row = rowin + (mat >> 1) * 8;
    const int b_kof = (mat & 1) * 16;

    load_stage(0, 0);
    load_stage(1, 1);

    for (int it = 0; it < 32; it++) {
        int buf = it % 3;
        if (it < 31) { CPWAIT1(); } else { CPWAIT0(); }
        __syncthreads();
        uint32_t sb = smem_u + buf * STAGE;
        #pragma unroll
        for (int ks = 0; ks < 2; ks++) {
            uint32_t ahi[4][4], alo[4][4];
            #pragma unroll
            for (int mt = 0; mt < 4; mt++) {
                uint32_t ar = sb + (m0 + mt * 16 + a_row) * GROWB
                              + ks * 32 + a_kof;
                ldsm_x4(ahi[mt], ar);
                ldsm_x4(alo[mt], ar + SA_SZ);
            }
            #pragma unroll
            for (int np = 0; np < 4; np++) {
                uint32_t br = sb + SB_OFF + (n0 + np * 16 + b_row) * GROWB
                              + ks * 32 + b_kof;
                uint32_t bhi[4], blo[4];
                ldsm_x4(bhi, br);
                ldsm_x4(blo, br + SB_SZ);
                #pragma unroll
                for (int h = 0; h < 2; h++) {
                    int nt = np * 2 + h;
                    #pragma unroll
                    for (int mt = 0; mt < 4; mt++) {
                        mma16816(acc[mt][nt], ahi[mt], bhi[2 * h], bhi[2 * h + 1]);
                        mma16816(acc[mt][nt], ahi[mt], blo[2 * h], blo[2 * h + 1]);
                        mma16816(acc[mt][nt], alo[mt], bhi[2 * h], bhi[2 * h + 1]);
                    }
                }
            }
        }
        if (it + 2 < 32) load_stage(it + 2, (it + 2) % 3);
    }

    // ---- epilogue
    const int sel = (MODE == 4) ? (bn >> 3) : 3;           // 0=Q 1=K 2=V
    const float* bias = (MODE == 3) ? bias0
                        : (sel == 0) ? bias0 : (sel == 1) ? bias1 : bias2;
    #pragma unroll
    for (int mt = 0; mt < 4; mt++) {
        #pragma unroll
        for (int nt = 0; nt < 8; nt++) {
            int n = (MODE == 4 ? (bn & 7) : bn) * 128 + n0 + nt * 8 + tig * 2;
            float bx = bias[n], by = bias[n + 1];
            #pragma unroll
            for (int half = 0; half < 2; half++) {
                int m = bm * 256 + m0 + mt * 16 + gid + half * 8;
                float vx = acc[mt][nt][half * 2 + 0] + bx;
                float vy = acc[mt][nt][half * 2 + 1] + by;
                if (MODE == 3) {
                    *reinterpret_cast<float2*>(&Cout[(size_t)m * E_ + n]) =
                        make_float2(vx, vy);
                } else {
                    int t = m >> 2, b = m & 3;
                    int h = n >> 6, d = n & 63;
                    size_t idx;
                    if (sel == 0) {
                        int x = b * 16 + (t >> 6);
                        int y = ((t & 63) << 4) | h;
                        idx = ((size_t)x * T_ + y) * HD + d;
                        vx *= QSCALE; vy *= QSCALE;
                        *reinterpret_cast<float2*>(&g_Qf[idx]) =
                            make_float2(vx, vy);
                    } else {
                        int u = t * 16 + h;
                        int x = b * 16 + u / 1025;
                        int y = u % 1025;
                        idx = ((size_t)x * SLEN + y) * HD + d;
                    }
                    uint32_t hi, lo;
                    split2(vx, vy, hi, lo);
                    __nv_bfloat16* ph = (sel == 0) ? g_Qh : (sel == 1) ? g_Kh : g_Vh;
                    __nv_bfloat16* pl = (sel == 0) ? g_Ql : (sel == 1) ? g_Kl : g_Vl;
                    *reinterpret_cast<uint32_t*>(&ph[idx]) = hi;
                    *reinterpret_cast<uint32_t*>(&pl[idx]) = lo;
                }
            }
        }
    }
}

// ---------------------------------------------------------------- small kernels
__global__ void biaskv_kernel(const float* __restrict__ bias_k,
                              const float* __restrict__ bias_v)
{
    int i = blockIdx.x * blockDim.x + threadIdx.x;
    if (i >= BZ * NH * HD) return;
    int b = i >> 10, h = (i >> 6) & 15, d = i & 63;
    int x = b * 16 + 15;
    int y = 1009 + h;
    size_t idx = ((size_t)x * SLEN + y) * HD + d;
    float kv = bias_k[h * HD + d];
    float vv = bias_v[h * HD + d];
    __nv_bfloat16 kh = __float2bfloat16(kv);
    __nv_bfloat16 vh = __float2bfloat16(vv);
    g_Kh[idx] = kh; g_Kl[idx] = __float2bfloat16(kv - __bfloat162float(kh));
    g_Vh[idx] = vh; g_Vl[idx] = __float2bfloat16(vv - __bfloat162float(vh));
}

__global__ void pb_kernel(const float* __restrict__ rel_emb)
{
    int d = blockIdx.x * blockDim.x + threadIdx.x;
    if (d >= 2048) return;
    int rel = d - 1023;
    int bkt = rel > 0 ? 16 : 0;
    int a = rel < 0 ? -rel : rel;
    int bu;
    if (a < 8) {
        bu = a;
    } else {
        float lf = logf((float)a * 0.125f + 1e-6f) * (8.0f / 2.772588722239781f);
        int large = 8 + (int)lf;
        bu = large < 15 ? large : 15;
    }
    int bucket = bkt + bu;
    #pragma unroll
    for (int h = 0; h < NH; h++)
        g_pb[h * 2048 + d] = rel_emb[bucket * NH + h];
}

__global__ __launch_bounds__(256)
void gate_kernel(const float* __restrict__ grep_w,
                 const float* __restrict__ grep_b,
                 const float* __restrict__ grep_a)
{
    __shared__ float gws[64];
    __shared__ float gbs;
    int tid = threadIdx.x;
    if (tid < 64) {
        float s = 0.f;
        #pragma unroll
        for (int j = 0; j < 8; j++) s += grep_w[tid * 8 + j];
        gws[tid] = s;
    }
    if (tid == 64) {
        float s = 0.f;
        #pragma unroll
        for (int j = 0; j < 8; j++) s += grep_b[j];
        gbs = s;
    }
    __syncthreads();
    int warp = tid >> 5, lane = tid & 31;
    int row = blockIdx.x * 8 + warp;
    if (row < BH * T_) {
        const float* q = &g_Qf[(size_t)row * HD];
        float s = q[lane] * gws[lane] + q[lane + 32] * gws[lane + 32];
        #pragma unroll
        for (int off = 16; off; off >>= 1)
            s += __shfl_xor_sync(0xffffffffu, s, off);
        if (lane == 0) {
            int hx = (row >> 10) & 15;
            float val = s * 256.0f + gbs;
            float sig = 1.0f / (1.0f + __expf(-val));
            g_gate[row] = sig * grep_a[hx];
        }
    }
}

// ---------------------------------------------------------------- attention (mma)
__global__ __launch_bounds__(128)
void attn_mma()
{
    extern __shared__ __align__(16) char asmm[];
    const uint32_t smem_u = cvta_smem(asmm);
    const int tid = threadIdx.x, lane = tid & 31, w = tid >> 5;
    const int gid = lane >> 2, tig = lane & 3;
    const int mat = lane >> 3, rowin = lane & 7;
    const int x = blockIdx.y, t0 = blockIdx.x * 64;
    const int hx = x & 15, bx = x >> 4;

    {
        const char* srcH = (const char*)g_Qh + ((size_t)x * T_ + t0) * HD * 2;
        const char* srcL = (const char*)g_Ql + ((size_t)x * T_ + t0) * HD * 2;
        #pragma unroll
        for (int i = 0; i < 8; i++) {
            int idx = tid + i * 128;
            int tile = idx >> 9, row = (idx >> 3) & 63, c = idx & 7;
            const char* s = (tile ? srcL : srcH) + (size_t)row * 128 + c * 16;
            uint32_t d = smem_u + (tile ? A_QL : A_QH) + row * AROW + c * 16;
            CP16(d, s);
        }
        CPCOMMIT();
    }

    const char* pKh = (const char*)g_Kh + (size_t)x * SLEN * HD * 2;
    const char* pKl = (const char*)g_Kl + (size_t)x * SLEN * HD * 2;
    const char* pVh = (const char*)g_Vh + (size_t)x * SLEN * HD * 2;
    const char* pVl = (const char*)g_Vl + (size_t)x * SLEN * HD * 2;

    auto load_kv = [&](int ch, int buf) {
        int s0 = ch * 64;
        #pragma unroll
        for (int i = 0; i < 16; i++) {
            int idx = tid + i * 128;
            int tile = idx >> 9, row = (idx >> 3) & 63, c = idx & 7;
            const char* p = (tile & 2) ? ((tile & 1) ? pVl : pVh)
                                       : ((tile & 1) ? pKl : pKh);
            uint32_t d = smem_u + A_ST + buf * A_STB + tile * ATILE
                         + row * AROW + c * 16;
            CP16(d, p + ((size_t)(s0 + row)) * 128 + c * 16);
        }
        CPCOMMIT();
    };

    load_kv(0, 0);

    float m0 = -1e30f, m1 = -1e30f, l0 = 0.f, l1 = 0.f;
    float o[8][4] = {};
    uint32_t qh[4][4], ql[4][4];
    const int tg0 = t0 + w * 16 + gid;
    const float gate0 = g_gate[(size_t)x * T_ + tg0];
    const float gate1 = g_gate[(size_t)x * T_ + tg0 + 8];

    for (int ch = 0; ch < 17; ch++) {
        int buf = ch & 1;
        if (ch + 1 < 17) { load_kv(ch + 1, buf ^ 1); CPWAIT1(); }
        else             { CPWAIT0(); }
        __syncthreads();

        if (ch == 0) {
            #pragma unroll
            for (int ks = 0; ks < 4; ks++) {
                uint32_t qa = smem_u + A_QH
                    + (w * 16 + rowin + (mat & 1) * 8) * AROW
                    + ks * 32 + (mat >> 1) * 16;
                ldsm_x4(qh[ks], qa);
                ldsm_x4(ql[ks], qa + ATILE);
            }
        }

        const uint32_t kb = smem_u + A_ST + buf * A_STB;

        float s_acc[8][4] = {};
        #pragma unroll
        for (int ks = 0; ks < 4; ks++) {
            #pragma unroll
            for (int np = 0; np < 4; np++) {
                uint32_t ka = kb + (np * 16 + rowin + (mat >> 1) * 8) * AROW
                              + ks * 32 + (mat & 1) * 16;
                uint32_t khf[4], klf[4];
                ldsm_x4(khf, ka);
                ldsm_x4(klf, ka + ATILE);
                #pragma unroll
                for (int h2 = 0; h2 < 2; h2++) {
                    int nt = np * 2 + h2;
                    mma16816(s_acc[nt], qh[ks], khf[2 * h2], khf[2 * h2 + 1]);
                    mma16816(s_acc[nt], qh[ks], klf[2 * h2], klf[2 * h2 + 1]);
                    mma16816(s_acc[nt], ql[ks], khf[2 * h2], khf[2 * h2 + 1]);
                }
            }
        }

        int s0 = ch * 64;
        #pragma unroll
        for (int nt = 0; nt < 8; nt++) {
            #pragma unroll
            for (int j = 0; j < 4; j++) {
                int sg = s0 + nt * 8 + tig * 2 + (j & 1);
                int tg = tg0 + (j >> 1) * 8;
                float g = (j >> 1) ? gate1 : gate0;
                if (sg < SLEN)
                    s_acc[nt][j] += g * __ldg(&g_pb[hx * 2048 + sg - tg + 1023]);
                else
                    s_acc[nt][j] = -1e30f;
            }
        }

        float mx0 = -1e30f, mx1 = -1e30f;
        #pragma unroll
        for (int nt = 0; nt < 8; nt++) {
            mx0 = fmaxf(mx0, fmaxf(s_acc[nt][0], s_acc[nt][1]));
            mx1 = fmaxf(mx1, fmaxf(s_acc[nt][2], s_acc[nt][3]));
        }
        mx0 = fmaxf(mx0, __shfl_xor_sync(0xffffffffu, mx0, 1));
        mx0 = fmaxf(mx0, __shfl_xor_sync(0xffffffffu, mx0, 2));
        mx1 = fmaxf(mx1, __shfl_xor_sync(0xffffffffu, mx1, 1));
        mx1 = fmaxf(mx1, __shfl_xor_sync(0xffffffffu, mx1, 2));
        float mn0 = fmaxf(m0, mx0), mn1 = fmaxf(m1, mx1);
        float al0 = __expf(m0 - mn0), al1 = __expf(m1 - mn1);
        m0 = mn0; m1 = mn1;

        float sum0 = 0.f, sum1 = 0.f;
        #pragma unroll
        for (int nt = 0; nt < 8; nt++) {
            float p0 = __expf(s_acc[nt][0] - mn0);
            float p1 = __expf(s_acc[nt][1] - mn0);
            float p2 = __expf(s_acc[nt][2] - mn1);
            float p3 = __expf(s_acc[nt][3] - mn1);
            s_acc[nt][0] = p0; s_acc[nt][1] = p1;
            s_acc[nt][2] = p2; s_acc[nt][3] = p3;
            sum0 += p0 + p1; sum1 += p2 + p3;
        }
        sum0 += __shfl_xor_sync(0xffffffffu, sum0, 1);
        sum0 += __shfl_xor_sync(0xffffffffu, sum0, 2);
        sum1 += __shfl_xor_sync(0xffffffffu, sum1, 1);
        sum1 += __shfl_xor_sync(0xffffffffu, sum1, 2);
        l0 = l0 * al0 + sum0;
        l1 = l1 * al1 + sum1;

        #pragma unroll
        for (int nt = 0; nt < 8; nt++) {
            o[nt][0] *= al0; o[nt][1] *= al0;
            o[nt][2] *= al1; o[nt][3] *= al1;
        }

        const uint32_t vb = kb + 2 * ATILE;
        #pragma unroll
        for (int ks = 0; ks < 4; ks++) {
            uint32_t ah[4], al[4];
            #pragma unroll
            for (int q = 0; q < 4; q++) {
                int nt = 2 * ks + (q >> 1);
                float vx = s_acc[nt][(q & 1) * 2];
                float vy = s_acc[nt][(q & 1) * 2 + 1];
                split2(vx, vy, ah[q], al[q]);
            }
            #pragma unroll
            for (int np = 0; np < 4; np++) {
                uint32_t va = vb + (ks * 16 + rowin + (mat & 1) * 8) * AROW
                              + (np * 16 + (mat >> 1) * 8) * 2;
                uint32_t vhf[4], vlf[4];
                ldsm_x4_t(vhf, va);
                ldsm_x4_t(vlf, va + ATILE);
                #pragma unroll
                for (int h2 = 0; h2 < 2; h2++) {
                    int nt = np * 2 + h2;
                    mma16816(o[nt], ah, vhf[2 * h2], vhf[2 * h2 + 1]);
                    mma16816(o[nt], ah, vlf[2 * h2], vlf[2 * h2 + 1]);
                    mma16816(o[nt], al, vhf[2 * h2], vhf[2 * h2 + 1]);
                }
            }
        }
        __syncthreads();
    }

    float inv0 = 1.0f / l0, inv1 = 1.0f / l1;
    int y0 = tg0, y1 = tg0 + 8;
    #pragma unroll
    for (int nt = 0; nt < 8; nt++) {
        int col = hx * 64 + nt * 8 + tig * 2;
        uint32_t hi, lo;
        split2(o[nt][0] * inv0, o[nt][1] * inv0, hi, lo);
        size_t i0 = (size_t)(y0 * BZ + bx) * E_ + col;
        *reinterpret_cast<uint32_t*>(&g_Ahi[i0]) = hi;
        *reinterpret_cast<uint32_t*>(&g_Alo[i0]) = lo;
        split2(o[nt][2] * inv1, o[nt][3] * inv1, hi, lo);
        size_t i1 = (size_t)(y1 * BZ + bx) * E_ + col;
        *reinterpret_cast<uint32_t*>(&g_Ahi[i1]) = hi;
        *reinterpret_cast<uint32_t*>(&g_Alo[i1]) = lo;
    }
}

// ---------------------------------------------------------------- host side
extern "C" void kernel_launch(void* const* d_in, const int* in_sizes, int n_in,
                              void* d_out, int out_size)
{
    (void)in_sizes; (void)n_in; (void)out_size;
    const float* query   = (const float*)d_in[0];
    const float* q_w     = (const float*)d_in[1];
    const float* q_b     = (const float*)d_in[2];
    const float* k_w     = (const float*)d_in[3];
    const float* k_b     = (const float*)d_in[4];
    const float* v_w     = (const float*)d_in[5];
    const float* v_b     = (const float*)d_in[6];
    const float* out_w   = (const float*)d_in[7];
    const float* out_b   = (const float*)d_in[8];
    const float* rel_emb = (const float*)d_in[9];
    const float* grep_w  = (const float*)d_in[10];
    const float* grep_b  = (const float*)d_in[11];
    const float* grep_a  = (const float*)d_in[12];
    const float* bias_k  = (const float*)d_in[13];
    const float* bias_v  = (const float*)d_in[14];
    float* out = (float*)d_out;

    void *pAhi, *pAlo, *pWhi, *pWlo;
    cudaGetSymbolAddress(&pAhi, g_Ahi);
    cudaGetSymbolAddress(&pAlo, g_Alo);
    cudaGetSymbolAddress(&pWhi, g_Whi);
    cudaGetSymbolAddress(&pWlo, g_Wlo);

    __nv_bfloat16* Ahi = (__nv_bfloat16*)pAhi;
    __nv_bfloat16* Alo = (__nv_bfloat16*)pAlo;
    const size_t wsz = (size_t)E_ * E_;
    __nv_bfloat16* Whi = (__nv_bfloat16*)pWhi;
    __nv_bfloat16* Wlo = (__nv_bfloat16*)pWlo;

    cudaFuncSetAttribute((const void*)mma_gemm<3>,
        cudaFuncAttributeMaxDynamicSharedMemorySize, GEMM_SMEM);
    cudaFuncSetAttribute((const void*)mma_gemm<4>,
        cudaFuncAttributeMaxDynamicSharedMemorySize, GEMM_SMEM);
    cudaFuncSetAttribute((const void*)attn_mma,
        cudaFuncAttributeMaxDynamicSharedMemorySize, ATTN_SMEM);

    // launch order keeps the QKV GEMM at slot #4 (ncu capture position)
    split_kernel<<<4096, 256>>>(query, Ahi, Alo, M_ * E_ / 4);          // 1
    transW_all<<<dim3(32, 32, 4), dim3(32, 8)>>>(q_w, k_w, v_w, out_w); // 2
    biaskv_kernel<<<16, 256>>>(bias_k, bias_v);                         // 3
    mma_gemm<4><<<dim3(24, 16), 256, GEMM_SMEM>>>(                      // 4
        Ahi, Alo, Whi, Wlo, q_b, k_b, v_b, nullptr);
    pb_kernel<<<8, 256>>>(rel_emb);                                     // 5
    gate_kernel<<<8192, 256>>>(grep_w, grep_b, grep_a);                 // 6
    attn_mma<<<dim3(16, 64), 128, ATTN_SMEM>>>();                       // 7
    mma_gemm<3><<<dim3(8, 16), 256, GEMM_SMEM>>>(                       // 8
        Ahi, Alo, Whi + 3 * wsz, Wlo + 3 * wsz, out_b, nullptr, nullptr, out);
}

// round 7
// speedup vs baseline: 4.1061x; 1.3280x over previous
#include <cuda_runtime.h>
#include <cuda_bf16.h>
#include <cstdint>

// ---------------------------------------------------------------- constants
#define T_   1024
#define BZ   4
#define E_   1024
#define NH   16
#define HD   64
#define BH   64          // bsz * nh
#define SLEN 1025        // src_len = T + 1 (bias_kv)
#define M_   4096        // rows of the projection GEMMs
#define QSCALE 0.00390625f   // hd^-0.5 / ALPHA = 1/256

// GEMM tiling: CTA 256x128, 8 warps (4x2), warp 64x64, K-chunk 32 bf16
#define GROWB 80                   // padded smem row bytes
#define SA_SZ (256 * GROWB)        // 20480
#define SB_SZ (128 * GROWB)        // 10240
#define SB_OFF (2 * SA_SZ)         // heavy: after Ahi+Alo
#define STAGE (2 * SA_SZ + 2 * SB_SZ)   // 61440 (heavy)
#define LSB_OFF SA_SZ              // light: after Ahi
#define LSTAGE (SA_SZ + SB_SZ)     // 30720 (light)
#define GEMM_SMEM (3 * STAGE)      // 184320

// attention smem: Q(hi) tile + gate region + 2 stages x {KH, VH, VL}
#define AROW  144
#define ATILE (64 * AROW)          // 9216
#define A_GT  9216                 // gate[64], gws[64], misc[2]
#define A_ST  10240
#define A_STB (3 * ATILE)          // 27648
#define ATTN_SMEM (A_ST + 2 * A_STB)   // 65536

#define KVSZ ((size_t)BH * SLEN * HD + 8192)

// ---------------------------------------------------------------- scratch
__device__ __nv_bfloat16 g_Qh[(size_t)BH * T_ * HD];
__device__ __nv_bfloat16 g_Kh[KVSZ];
__device__ __nv_bfloat16 g_Vh[KVSZ], g_Vl[KVSZ];
__device__ float g_pb[(size_t)NH * 2048];

__device__ __nv_bfloat16 g_Ahi[(size_t)M_ * E_];   // GEMM A (query, then O)
__device__ __nv_bfloat16 g_Alo[(size_t)M_ * E_];
__device__ __nv_bfloat16 g_Whi[4][(size_t)E_ * E_];  // q,k,v contiguous + out
__device__ __nv_bfloat16 g_Wlo[4][(size_t)E_ * E_];

// ---------------------------------------------------------------- helpers
__device__ __forceinline__ uint32_t cvta_smem(const void* p) {
    uint32_t a;
    asm("{ .reg .u64 t; cvta.to.shared.u64 t, %1; cvt.u32.u64 %0, t; }"
        : "=r"(a) : "l"(p));
    return a;
}

#define CP16(dst, src) \
    asm volatile("cp.async.cg.shared.global [%0], [%1], 16;" \
        :: "r"(dst), "l"(src) : "memory")
#define CPCOMMIT() asm volatile("cp.async.commit_group;" ::: "memory")
#define CPWAIT1()  asm volatile("cp.async.wait_group 1;" ::: "memory")
#define CPWAIT0()  asm volatile("cp.async.wait_group 0;" ::: "memory")

__device__ __forceinline__ void ldsm_x4(uint32_t r[4], uint32_t addr) {
    asm volatile(
        "ldmatrix.sync.aligned.m8n8.x4.shared.b16 {%0,%1,%2,%3}, [%4];"
        : "=r"(r[0]), "=r"(r[1]), "=r"(r[2]), "=r"(r[3]) : "r"(addr));
}
__device__ __forceinline__ void ldsm_x4_t(uint32_t r[4], uint32_t addr) {
    asm volatile(
        "ldmatrix.sync.aligned.m8n8.x4.trans.shared.b16 {%0,%1,%2,%3}, [%4];"
        : "=r"(r[0]), "=r"(r[1]), "=r"(r[2]), "=r"(r[3]) : "r"(addr));
}

__device__ __forceinline__ void mma16816(float c[4], const uint32_t a[4],
                                         uint32_t b0, uint32_t b1) {
    asm volatile(
        "mma.sync.aligned.m16n8k16.row.col.f32.bf16.bf16.f32 "
        "{%0,%1,%2,%3}, {%4,%5,%6,%7}, {%8,%9}, {%0,%1,%2,%3};"
        : "+f"(c[0]), "+f"(c[1]), "+f"(c[2]), "+f"(c[3])
        : "r"(a[0]), "r"(a[1]), "r"(a[2]), "r"(a[3]), "r"(b0), "r"(b1));
}

__device__ __forceinline__ uint32_t packbf(__nv_bfloat16 a, __nv_bfloat16 b) {
    __nv_bfloat162 t(a, b);
    return *reinterpret_cast<uint32_t*>(&t);
}

__device__ __forceinline__ void split2(float x, float y,
                                       uint32_t& hi, uint32_t& lo) {
    __nv_bfloat16 hx = __float2bfloat16(x);
    __nv_bfloat16 hy = __float2bfloat16(y);
    __nv_bfloat16 lx = __float2bfloat16(x - __bfloat162float(hx));
    __nv_bfloat16 ly = __float2bfloat16(y - __bfloat162float(hy));
    hi = packbf(hx, hy);
    lo = packbf(lx, ly);
}

// ---------------------------------------------------------------- bf16 split
__global__ __launch_bounds__(256)
void split_kernel(const float* __restrict__ src,
                  __nv_bfloat16* __restrict__ hi,
                  __nv_bfloat16* __restrict__ lo, int n4)
{
    int i = blockIdx.x * blockDim.x + threadIdx.x;
    if (i >= n4) return;
    float4 v = reinterpret_cast<const float4*>(src)[i];
    uint32_t h0, l0, h1, l1;
    split2(v.x, v.y, h0, l0);
    split2(v.z, v.w, h1, l1);
    uint32_t* hp = reinterpret_cast<uint32_t*>(hi);
    uint32_t* lp = reinterpret_cast<uint32_t*>(lo);
    hp[2 * i] = h0; hp[2 * i + 1] = h1;
    lp[2 * i] = l0; lp[2 * i + 1] = l1;
}

// transpose + split all 4 weights (z = which matrix)
__global__ __launch_bounds__(256)
void transW_all(const float* __restrict__ w0, const float* __restrict__ w1,
                const float* __restrict__ w2, const float* __restrict__ w3)
{
    __shared__ float tile[32][33];
    int tx = threadIdx.x, ty = threadIdx.y;          // 32 x 8
    int bx = blockIdx.x * 32, by = blockIdx.y * 32;
    int z = blockIdx.z;
    const float* W = (z == 0) ? w0 : (z == 1) ? w1 : (z == 2) ? w2 : w3;
    __nv_bfloat16* hi = g_Whi[z];
    __nv_bfloat16* lo = g_Wlo[z];
    #pragma unroll
    for (int r = 0; r < 4; r++)
        tile[ty + r * 8][tx] = W[(size_t)(by + ty + r * 8) * E_ + bx + tx];
    __syncthreads();
    #pragma unroll
    for (int r = 0; r < 4; r++) {
        int n = bx + ty + r * 8, k = by + tx;
        float v = tile[tx][ty + r * 8];
        __nv_bfloat16 h = __float2bfloat16(v);
        hi[(size_t)n * E_ + k] = h;
        lo[(size_t)n * E_ + k] = __float2bfloat16(v - __bfloat162float(h));
    }
}

// ---------------------------------------------------------------- prep (pb + bias_kv)
__global__ void prep_kernel(const float* __restrict__ rel_emb,
                            const float* __restrict__ bias_k,
                            const float* __restrict__ bias_v)
{
    int i = blockIdx.x * blockDim.x + threadIdx.x;   // 4096 threads
    if (i < 2048) {
        int rel = i - 1023;
        int bkt = rel > 0 ? 16 : 0;
        int a = rel < 0 ? -rel : rel;
        int bu;
        if (a < 8) {
            bu = a;
        } else {
            float lf = logf((float)a * 0.125f + 1e-6f)
                       * (8.0f / 2.772588722239781f);
            int large = 8 + (int)lf;
            bu = large < 15 ? large : 15;
        }
        int bucket = bkt + bu;
        #pragma unroll
        for (int h = 0; h < NH; h++)
            g_pb[h * 2048 + i] = rel_emb[bucket * NH + h];
    }
    // bias_kv row
    int b = i >> 10, h = (i >> 6) & 15, d = i & 63;
    int x = b * 16 + 15;
    int y = 1009 + h;
    size_t idx = ((size_t)x * SLEN + y) * HD + d;
    float kv = bias_k[h * HD + d];
    float vv = bias_v[h * HD + d];
    __nv_bfloat16 vh = __float2bfloat16(vv);
    g_Kh[idx] = __float2bfloat16(kv);
    g_Vh[idx] = vh;
    g_Vl[idx] = __float2bfloat16(vv - __bfloat162float(vh));
}

// ---------------------------------------------------------------- mma GEMM
// MODE 4: fused QKV. bn 0-7 -> Q (light, 1-term), 8-15 -> K (light),
//         16-23 -> V (heavy, 3-term split).
// MODE 3: out proj (heavy) -> Cout f32 row-major
template<int MODE>
__global__ __launch_bounds__(256, 1)
void mma_gemm(const __nv_bfloat16* __restrict__ Ahi,
              const __nv_bfloat16* __restrict__ Alo,
              const __nv_bfloat16* __restrict__ Bhi,
              const __nv_bfloat16* __restrict__ Blo,
              const float* __restrict__ bias0,
              const float* __restrict__ bias1,
              const float* __restrict__ bias2,
              float* __restrict__ Cout)
{
    extern __shared__ __align__(16) char sm_[];
    const int tid = threadIdx.x, lane = tid & 31, w = tid >> 5;
    const int bn = blockIdx.x, bm = blockIdx.y;
    const uint32_t smem_u = cvta_smem(sm_);

    const int wm = w >> 1, wn = w & 1;
    const int m0 = wm * 64, n0 = wn * 64;
    const int gid = lane >> 2, tig = lane & 3;
    const int mat = lane >> 3, rowin = lane & 7;
    const int a_row = rowin + (mat & 1) * 8;
    const int a_kof = (mat >> 1) * 16;
    const int b_row = rowin + (mat >> 1) * 8;
    const int b_kof = (mat & 1) * 16;

    const char* gA0 = (const char*)(Ahi + (size_t)(bm * 256) * 1024);
    const char* gA1 = (const char*)(Alo + (size_t)(bm * 256) * 1024);
    const char* gB0 = (const char*)(Bhi + (size_t)(bn * 128) * 1024);
    const char* gB1 = (const char*)(Blo + (size_t)(bn * 128) * 1024);

    const bool light = (MODE == 4) && (bn < 16);

    if (light) {
        // ---------------- light path: C = Ahi @ Bhi^T (1 mma per tile)
        auto load_l = [&](int it, int buf) {
            uint32_t sb = smem_u + buf * LSTAGE;
            const int kb = it * 64;
            #pragma unroll
            for (int i = 0; i < 6; i++) {
                int idx = tid + i * 256;
                if (idx < 1024) {
                    int row = idx >> 2, c = idx & 3;
                    CP16(sb + row * GROWB + c * 16,
                         gA0 + (size_t)row * 2048 + kb + c * 16);
                } else {
                    int i2 = idx - 1024;
                    int row = i2 >> 2, c = i2 & 3;
                    CP16(sb + LSB_OFF + row * GROWB + c * 16,
                         gB0 + (size_t)row * 2048 + kb + c * 16);
                }
            }
            CPCOMMIT();
        };

        float acc[4][8][4] = {};
        load_l(0, 0);
        load_l(1, 1);

        for (int it = 0; it < 32; it++) {
            int buf = it % 3;
            if (it < 31) { CPWAIT1(); } else { CPWAIT0(); }
            __syncthreads();
            uint32_t sb = smem_u + buf * LSTAGE;
            #pragma unroll
            for (int ks = 0; ks < 2; ks++) {
                uint32_t ahi[4][4];
                #pragma unroll
                for (int mt = 0; mt < 4; mt++)
                    ldsm_x4(ahi[mt], sb + (m0 + mt * 16 + a_row) * GROWB
                                     + ks * 32 + a_kof);
                #pragma unroll
                for (int np = 0; np < 4; np++) {
                    uint32_t bhi[4];
                    ldsm_x4(bhi, sb + LSB_OFF
                                 + (n0 + np * 16 + b_row) * GROWB
                                 + ks * 32 + b_kof);
                    #pragma unroll
                    for (int h = 0; h < 2; h++)
                        #pragma unroll
                        for (int mt = 0; mt < 4; mt++)
                            mma16816(acc[mt][np * 2 + h], ahi[mt],
                                     bhi[2 * h], bhi[2 * h + 1]);
                }
            }
            if (it + 2 < 32) load_l(it + 2, (it + 2) % 3);
        }

        // epilogue: Q (bn<8) or K
        const int sel = bn >> 3;                    // 0=Q, 1=K
        const float* bias = (sel == 0) ? bias0 : bias1;
        #pragma unroll
        for (int mt = 0; mt < 4; mt++) {
            #pragma unroll
            for (int nt = 0; nt < 8; nt++) {
                int n = (bn & 7) * 128 + n0 + nt * 8 + tig * 2;
                float bx = bias[n], by = bias[n + 1];
                #pragma unroll
                for (int half = 0; half < 2; half++) {
                    int m = bm * 256 + m0 + mt * 16 + gid + half * 8;
                    float vx = acc[mt][nt][half * 2 + 0] + bx;
                    float vy = acc[mt][nt][half * 2 + 1] + by;
                    int t = m >> 2, b = m & 3;
                    int h = n >> 6, d = n & 63;
                    if (sel == 0) {
                        int x = b * 16 + (t >> 6);
                        int y = ((t & 63) << 4) | h;
                        size_t idx = ((size_t)x * T_ + y) * HD + d;
                        uint32_t hi = packbf(__float2bfloat16(vx * QSCALE),
                                             __float2bfloat16(vy * QSCALE));
                        *reinterpret_cast<uint32_t*>(&g_Qh[idx]) = hi;
                    } else {
                        int u = t * 16 + h;
                        int x = b * 16 + u / 1025;
                        int y = u % 1025;
                        size_t idx = ((size_t)x * SLEN + y) * HD + d;
                        uint32_t hi = packbf(__float2bfloat16(vx),
                                             __float2bfloat16(vy));
                        *reinterpret_cast<uint32_t*>(&g_Kh[idx]) = hi;
                    }
                }
            }
        }
        return;
    }

    // ---------------- heavy path: 3-term bf16 split (V proj / out proj)
    auto load_stage = [&](int it, int buf) {
        uint32_t sb = smem_u + buf * STAGE;
        const int kb = it * 64;
        #pragma unroll
        for (int i = 0; i < 12; i++) {
            int idx = tid + i * 256;
            if (idx < 2048) {
                int tile = idx >> 10, row = (idx >> 2) & 255, c = idx & 3;
                const char* g = (tile ? gA1 : gA0)
                                + (size_t)row * 2048 + kb + c * 16;
                CP16(sb + tile * SA_SZ + row * GROWB + c * 16, g);
            } else {
                int i2 = idx - 2048;
                int tile = i2 >> 9, row = (i2 >> 2) & 127, c = i2 & 3;
                const char* g = (tile ? gB1 : gB0)
                                + (size_t)row * 2048 + kb + c * 16;
                CP16(sb + SB_OFF + tile * SB_SZ + row * GROWB + c * 16, g);
            }
        }
        CPCOMMIT();
    };

    float acc[4][8][4] = {};
    load_stage(0, 0);
    load_stage(1, 1);

    for (int it = 0; it < 32; it++) {
        int buf = it % 3;
        if (it < 31) { CPWAIT1(); } else { CPWAIT0(); }
        __syncthreads();
        uint32_t sb = smem_u + buf * STAGE;
        #pragma unroll
        for (int ks = 0; ks < 2; ks++) {
            uint32_t ahi[4][4], alo[4][4];
            #pragma unroll
            for (int mt = 0; mt < 4; mt++) {
                uint32_t ar = sb + (m0 + mt * 16 + a_row) * GROWB
                              + ks * 32 + a_kof;
                ldsm_x4(ahi[mt], ar);
                ldsm_x4(alo[mt], ar + SA_SZ);
            }
            #pragma unroll
            for (int np = 0; np < 4; np++) {
                uint32_t br = sb + SB_OFF + (n0 + np * 16 + b_row) * GROWB
                              + ks * 32 + b_kof;
                uint32_t bhi[4], blo[4];
                ldsm_x4(bhi, br);
                ldsm_x4(blo, br + SB_SZ);
                #pragma unroll
                for (int h = 0; h < 2; h++) {
                    int nt = np * 2 + h;
                    // term-major ordering: consecutive mmas hit different acc
                    #pragma unroll
                    for (int mt = 0; mt < 4; mt++)
                        mma16816(acc[mt][nt], ahi[mt], bhi[2 * h], bhi[2 * h + 1]);
                    #pragma unroll
                    for (int mt = 0; mt < 4; mt++)
                        mma16816(acc[mt][nt], ahi[mt], blo[2 * h], blo[2 * h + 1]);
                    #pragma unroll
                    for (int mt = 0; mt < 4; mt++)
                        mma16816(acc[mt][nt], alo[mt], bhi[2 * h], bhi[2 * h + 1]);
                }
            }
        }
        if (it + 2 < 32) load_stage(it + 2, (it + 2) % 3);
    }

    // ---- epilogue (heavy): V proj scatter or out-proj store
    const float* bias = (MODE == 3) ? bias0 : bias2;
    #pragma unroll
    for (int mt = 0; mt < 4; mt++) {
        #pragma unroll
        for (int nt = 0; nt < 8; nt++) {
            int n = (MODE == 4 ? (bn & 7) : bn) * 128 + n0 + nt * 8 + tig * 2;
            float bx = bias[n], by = bias[n + 1];
            #pragma unroll
            for (int half = 0; half < 2; half++) {
                int m = bm * 256 + m0 + mt * 16 + gid + half * 8;
                float vx = acc[mt][nt][half * 2 + 0] + bx;
                float vy = acc[mt][nt][half * 2 + 1] + by;
                if (MODE == 3) {
                    *reinterpret_cast<float2*>(&Cout[(size_t)m * E_ + n]) =
                        make_float2(vx, vy);
                } else {
                    int t = m >> 2, b = m & 3;
                    int h = n >> 6, d = n & 63;
                    int u = t * 16 + h;
                    int x = b * 16 + u / 1025;
                    int y = u % 1025;
                    size_t idx = ((size_t)x * SLEN + y) * HD + d;
                    uint32_t hi, lo;
                    split2(vx, vy, hi, lo);
                    *reinterpret_cast<uint32_t*>(&g_Vh[idx]) = hi;
                    *reinterpret_cast<uint32_t*>(&g_Vl[idx]) = lo;
                }
            }
        }
    }
}

// ---------------------------------------------------------------- attention
// 64 q-rows per CTA, 4 warps. QK^T: bf16 1-term. PV: bf16x3.
// Gate computed in-kernel from Q smem tile.
__global__ __launch_bounds__(128, 3)
void attn_mma(const float* __restrict__ grep_w,
              const float* __restrict__ grep_b,
              const float* __restrict__ grep_a)
{
    extern __shared__ __align__(16) char asmm[];
    const uint32_t smem_u = cvta_smem(asmm);
    const int tid = threadIdx.x, lane = tid & 31, w = tid >> 5;
    const int gid = lane >> 2, tig = lane & 3;
    const int mat = lane >> 3, rowin = lane & 7;
    const int x = blockIdx.y, t0 = blockIdx.x * 64;
    const int hx = x & 15, bx = x >> 4;

    float* gate_s = reinterpret_cast<float*>(asmm + A_GT);   // [64]
    float* gws_s  = gate_s + 64;                              // [64]
    float* misc_s = gws_s + 64;                               // [2]

    if (tid < 64) {
        float s = 0.f;
        #pragma unroll
        for (int j = 0; j < 8; j++) s += grep_w[tid * 8 + j];
        gws_s[tid] = s;
    }
    if (tid == 64) {
        float s = 0.f;
        #pragma unroll
        for (int j = 0; j < 8; j++) s += grep_b[j];
        misc_s[0] = s;
    }
    if (tid == 65) misc_s[1] = grep_a[hx];

    // Q tile (hi only): 64 rows x 128B
    {
        const char* srcH = (const char*)g_Qh + ((size_t)x * T_ + t0) * HD * 2;
        #pragma unroll
        for (int i = 0; i < 4; i++) {
            int idx = tid + i * 128;
            int row = idx >> 3, c = idx & 7;
            CP16(smem_u + row * AROW + c * 16,
                 srcH + (size_t)row * 128 + c * 16);
        }
        CPCOMMIT();
    }

    const char* pKh = (const char*)g_Kh + (size_t)x * SLEN * HD * 2;
    const char* pVh = (const char*)g_Vh + (size_t)x * SLEN * HD * 2;
    const char* pVl = (const char*)g_Vl + (size_t)x * SLEN * HD * 2;

    auto load_kv = [&](int ch, int buf) {
        int s0 = ch * 64;
        #pragma unroll
        for (int i = 0; i < 12; i++) {
            int idx = tid + i * 128;
            int tile = idx >> 9, row = (idx >> 3) & 63, c = idx & 7;
            const char* p = (tile == 0) ? pKh : (tile == 1) ? pVh : pVl;
            CP16(smem_u + A_ST + buf * A_STB + tile * ATILE
                 + row * AROW + c * 16,
                 p + (size_t)(s0 + row) * 128 + c * 16);
        }
        CPCOMMIT();
    };

    load_kv(0, 0);

    // wait for Q (leave kv0 in flight), then compute gates from Q smem
    CPWAIT1();
    __syncthreads();
    {
        int r = tid >> 1, hf = tid & 1;
        const __nv_bfloat16* qr =
            reinterpret_cast<const __nv_bfloat16*>(asmm + r * AROW) + hf * 32;
        float s = 0.f;
        #pragma unroll
        for (int d2 = 0; d2 < 32; d2++)
            s += __bfloat162float(qr[d2]) * gws_s[hf * 32 + d2];
        s += __shfl_xor_sync(0xffffffffu, s, 1);
        if (hf == 0)
            gate_s[r] = misc_s[1] / (1.f + __expf(-(s * 256.f + misc_s[0])));
    }

    float m0 = -1e30f, m1 = -1e30f, l0 = 0.f, l1 = 0.f;
    float o[8][4] = {};
    uint32_t qh[4][4];
    const int tg0 = t0 + w * 16 + gid;
    float gate0 = 0.f, gate1 = 0.f;

    for (int ch = 0; ch < 17; ch++) {
        int buf = ch & 1;
        if (ch + 1 < 17) { load_kv(ch + 1, buf ^ 1); CPWAIT1(); }
        else             { CPWAIT0(); }
        __syncthreads();

        if (ch == 0) {
            #pragma unroll
            for (int ks = 0; ks < 4; ks++)
                ldsm_x4(qh[ks], smem_u
                        + (w * 16 + rowin + (mat & 1) * 8) * AROW
                        + ks * 32 + (mat >> 1) * 16);
            gate0 = gate_s[w * 16 + gid];
            gate1 = gate_s[w * 16 + gid + 8];
        }

        const uint32_t kb = smem_u + A_ST + buf * A_STB;

        // ---- S = Q K^T (bf16 single-term)
        float s_acc[8][4] = {};
        #pragma unroll
        for (int ks = 0; ks < 4; ks++) {
            #pragma unroll
            for (int np = 0; np < 4; np++) {
                uint32_t khf[4];
                ldsm_x4(khf, kb + (np * 16 + rowin + (mat >> 1) * 8) * AROW
                             + ks * 32 + (mat & 1) * 16);
                #pragma unroll
                for (int h2 = 0; h2 < 2; h2++)
                    mma16816(s_acc[np * 2 + h2], qh[ks],
                             khf[2 * h2], khf[2 * h2 + 1]);
            }
        }

        // ---- gated position bias + mask
        int s0 = ch * 64;
        #pragma unroll
        for (int nt = 0; nt < 8; nt++) {
            #pragma unroll
            for (int j = 0; j < 4; j++) {
                int sg = s0 + nt * 8 + tig * 2 + (j & 1);
                int tg = tg0 + (j >> 1) * 8;
                float g = (j >> 1) ? gate1 : gate0;
                if (sg < SLEN)
                    s_acc[nt][j] += g * __ldg(&g_pb[hx * 2048 + sg - tg + 1023]);
                else
                    s_acc[nt][j] = -1e30f;
            }
        }

        // ---- online softmax
        float mx0 = -1e30f, mx1 = -1e30f;
        #pragma unroll
        for (int nt = 0; nt < 8; nt++) {
            mx0 = fmaxf(mx0, fmaxf(s_acc[nt][0], s_acc[nt][1]));
            mx1 = fmaxf(mx1, fmaxf(s_acc[nt][2], s_acc[nt][3]));
        }
        mx0 = fmaxf(mx0, __shfl_xor_sync(0xffffffffu, mx0, 1));
        mx0 = fmaxf(mx0, __shfl_xor_sync(0xffffffffu, mx0, 2));
        mx1 = fmaxf(mx1, __shfl_xor_sync(0xffffffffu, mx1, 1));
        mx1 = fmaxf(mx1, __shfl_xor_sync(0xffffffffu, mx1, 2));
        float mn0 = fmaxf(m0, mx0), mn1 = fmaxf(m1, mx1);
        float al0 = __expf(m0 - mn0), al1 = __expf(m1 - mn1);
        m0 = mn0; m1 = mn1;

        float sum0 = 0.f, sum1 = 0.f;
        #pragma unroll
        for (int nt = 0; nt < 8; nt++) {
            float p0 = __expf(s_acc[nt][0] - mn0);
            float p1 = __expf(s_acc[nt][1] - mn0);
            float p2 = __expf(s_acc[nt][2] - mn1);
            float p3 = __expf(s_acc[nt][3] - mn1);
            s_acc[nt][0] = p0; s_acc[nt][1] = p1;
            s_acc[nt][2] = p2; s_acc[nt][3] = p3;
            sum0 += p0 + p1; sum1 += p2 + p3;
        }
        sum0 += __shfl_xor_sync(0xffffffffu, sum0, 1);
        sum0 += __shfl_xor_sync(0xffffffffu, sum0, 2);
        sum1 += __shfl_xor_sync(0xffffffffu, sum1, 1);
        sum1 += __shfl_xor_sync(0xffffffffu, sum1, 2);
        l0 = l0 * al0 + sum0;
        l1 = l1 * al1 + sum1;

        #pragma unroll
        for (int nt = 0; nt < 8; nt++) {
            o[nt][0] *= al0; o[nt][1] *= al0;
            o[nt][2] *= al1; o[nt][3] *= al1;
        }

        // ---- O += P V (bf16x3)
        const uint32_t vbh = kb + ATILE;
        const uint32_t vbl = kb + 2 * ATILE;
        #pragma unroll
        for (int ks = 0; ks < 4; ks++) {
            uint32_t ah[4], al[4];
            #pragma unroll
            for (int q = 0; q < 4; q++) {
                int nt = 2 * ks + (q >> 1);
                split2(s_acc[nt][(q & 1) * 2], s_acc[nt][(q & 1) * 2 + 1],
                       ah[q], al[q]);
            }
            #pragma unroll
            for (int np = 0; np < 4; np++) {
                uint32_t va_off = (ks * 16 + rowin + (mat & 1) * 8) * AROW
                                  + (np * 16 + (mat >> 1) * 8) * 2;
                uint32_t vhf[4], vlf[4];
                ldsm_x4_t(vhf, vbh + va_off);
                ldsm_x4_t(vlf, vbl + va_off);
                #pragma unroll
                for (int h2 = 0; h2 < 2; h2++)
                    mma16816(o[np * 2 + h2], ah, vhf[2 * h2], vhf[2 * h2 + 1]);
                #pragma unroll
                for (int h2 = 0; h2 < 2; h2++)
                    mma16816(o[np * 2 + h2], ah, vlf[2 * h2], vlf[2 * h2 + 1]);
                #pragma unroll
                for (int h2 = 0; h2 < 2; h2++)
                    mma16816(o[np * 2 + h2], al, vhf[2 * h2], vhf[2 * h2 + 1]);
            }
        }
        __syncthreads();
    }

    // ---- epilogue: normalize, split, scatter to out-proj A operand
    float inv0 = 1.0f / l0, inv1 = 1.0f / l1;
    int y0 = tg0, y1 = tg0 + 8;
    #pragma unroll
    for (int nt = 0; nt < 8; nt++) {
        int col = hx * 64 + nt * 8 + tig * 2;
        uint32_t hi, lo;
        split2(o[nt][0] * inv0, o[nt][1] * inv0, hi, lo);
        size_t i0 = (size_t)(y0 * BZ + bx) * E_ + col;
        *reinterpret_cast<uint32_t*>(&g_Ahi[i0]) = hi;
        *reinterpret_cast<uint32_t*>(&g_Alo[i0]) = lo;
        split2(o[nt][2] * inv1, o[nt][3] * inv1, hi, lo);
        size_t i1 = (size_t)(y1 * BZ + bx) * E_ + col;
        *reinterpret_cast<uint32_t*>(&g_Ahi[i1]) = hi;
        *reinterpret_cast<uint32_t*>(&g_Alo[i1]) = lo;
    }
}

// ---------------------------------------------------------------- host side
extern "C" void kernel_launch(void* const* d_in, const int* in_sizes, int n_in,
                              void* d_out, int out_size)
{
    (void)in_sizes; (void)n_in; (void)out_size;
    const float* query   = (const float*)d_in[0];
    const float* q_w     = (const float*)d_in[1];
    const float* q_b     = (const float*)d_in[2];
    const float* k_w     = (const float*)d_in[3];
    const float* k_b     = (const float*)d_in[4];
    const float* v_w     = (const float*)d_in[5];
    const float* v_b     = (const float*)d_in[6];
    const float* out_w   = (const float*)d_in[7];
    const float* out_b   = (const float*)d_in[8];
    const float* rel_emb = (const float*)d_in[9];
    const float* grep_w  = (const float*)d_in[10];
    const float* grep_b  = (const float*)d_in[11];
    const float* grep_a  = (const float*)d_in[12];
    const float* bias_k  = (const float*)d_in[13];
    const float* bias_v  = (const float*)d_in[14];
    float* out = (float*)d_out;

    void *pAhi, *pAlo, *pWhi, *pWlo;
    cudaGetSymbolAddress(&pAhi, g_Ahi);
    cudaGetSymbolAddress(&pAlo, g_Alo);
    cudaGetSymbolAddress(&pWhi, g_Whi);
    cudaGetSymbolAddress(&pWlo, g_Wlo);

    __nv_bfloat16* Ahi = (__nv_bfloat16*)pAhi;
    __nv_bfloat16* Alo = (__nv_bfloat16*)pAlo;
    const size_t wsz = (size_t)E_ * E_;
    __nv_bfloat16* Whi = (__nv_bfloat16*)pWhi;
    __nv_bfloat16* Wlo = (__nv_bfloat16*)pWlo;

    cudaFuncSetAttribute((const void*)mma_gemm<3>,
        cudaFuncAttributeMaxDynamicSharedMemorySize, GEMM_SMEM);
    cudaFuncSetAttribute((const void*)mma_gemm<4>,
        cudaFuncAttributeMaxDynamicSharedMemorySize, GEMM_SMEM);
    cudaFuncSetAttribute((const void*)attn_mma,
        cudaFuncAttributeMaxDynamicSharedMemorySize, ATTN_SMEM);

    // slot 4 = qkv gemm (ncu capture position)
    split_kernel<<<4096, 256>>>(query, Ahi, Alo, M_ * E_ / 4);          // 1
    transW_all<<<dim3(32, 32, 4), dim3(32, 8)>>>(q_w, k_w, v_w, out_w); // 2
    prep_kernel<<<16, 256>>>(rel_emb, bias_k, bias_v);                  // 3
    mma_gemm<4><<<dim3(24, 16), 256, GEMM_SMEM>>>(                      // 4
        Ahi, Alo, Whi, Wlo, q_b, k_b, v_b, nullptr);
    attn_mma<<<dim3(16, 64), 128, ATTN_SMEM>>>(grep_w, grep_b, grep_a); // 5
    mma_gemm<3><<<dim3(8, 16), 256, GEMM_SMEM>>>(                       // 6
        Ahi, Alo, Whi + 3 * wsz, Wlo + 3 * wsz, out_b, nullptr, nullptr, out);
}

// round 8
// speedup vs baseline: 4.5640x; 1.1115x over previous
#include <cuda_runtime.h>
#include <cuda_bf16.h>
#include <cstdint>

// ---------------------------------------------------------------- constants
#define T_   1024
#define BZ   4
#define E_   1024
#define NH   16
#define HD   64
#define BH   64
#define SLEN 1025
#define M_   4096
#define QSCALE 0.00390625f

// GEMM tiling: CTA 256x128, 16 warps (8x2), warp 32x64, K-chunk 32 bf16
#define GROWB 80
#define SA_SZ (256 * GROWB)        // 20480
#define SB_SZ (128 * GROWB)        // 10240
#define SB_OFF (2 * SA_SZ)
#define STAGE (2 * SA_SZ + 2 * SB_SZ)   // 61440 (heavy)
#define LSB_OFF SA_SZ
#define LSTAGE (SA_SZ + SB_SZ)     // 30720 (light)
#define GEMM_SMEM (3 * STAGE)      // 184320
#define LGEMM_SMEM (3 * LSTAGE)    // 92160

// attention smem
#define AROW  144
#define ATILE (64 * AROW)
#define A_GT  9216
#define A_ST  10240
#define A_STB (3 * ATILE)
#define ATTN_SMEM (A_ST + 2 * A_STB)   // 65536

#define KVSZ ((size_t)BH * SLEN * HD + 8192)

// ---------------------------------------------------------------- scratch
__device__ __nv_bfloat16 g_Qh[(size_t)BH * T_ * HD];
__device__ __nv_bfloat16 g_Kh[KVSZ];
__device__ __nv_bfloat16 g_Vh[KVSZ], g_Vl[KVSZ];
__device__ float g_pb[(size_t)NH * 2048];

__device__ __nv_bfloat16 g_Ahi[(size_t)M_ * E_];
__device__ __nv_bfloat16 g_Alo[(size_t)M_ * E_];
__device__ __nv_bfloat16 g_Whi[4][(size_t)E_ * E_];
__device__ __nv_bfloat16 g_Wlo[4][(size_t)E_ * E_];

// ---------------------------------------------------------------- helpers
__device__ __forceinline__ uint32_t cvta_smem(const void* p) {
    uint32_t a;
    asm("{ .reg .u64 t; cvta.to.shared.u64 t, %1; cvt.u32.u64 %0, t; }"
        : "=r"(a) : "l"(p));
    return a;
}

#define CP16(dst, src) \
    asm volatile("cp.async.cg.shared.global [%0], [%1], 16;" \
        :: "r"(dst), "l"(src) : "memory")
#define CPCOMMIT() asm volatile("cp.async.commit_group;" ::: "memory")
#define CPWAIT1()  asm volatile("cp.async.wait_group 1;" ::: "memory")
#define CPWAIT0()  asm volatile("cp.async.wait_group 0;" ::: "memory")

__device__ __forceinline__ void ldsm_x4(uint32_t r[4], uint32_t addr) {
    asm volatile(
        "ldmatrix.sync.aligned.m8n8.x4.shared.b16 {%0,%1,%2,%3}, [%4];"
        : "=r"(r[0]), "=r"(r[1]), "=r"(r[2]), "=r"(r[3]) : "r"(addr));
}
__device__ __forceinline__ void ldsm_x4_t(uint32_t r[4], uint32_t addr) {
    asm volatile(
        "ldmatrix.sync.aligned.m8n8.x4.trans.shared.b16 {%0,%1,%2,%3}, [%4];"
        : "=r"(r[0]), "=r"(r[1]), "=r"(r[2]), "=r"(r[3]) : "r"(addr));
}

__device__ __forceinline__ void mma16816(float c[4], const uint32_t a[4],
                                         uint32_t b0, uint32_t b1) {
    asm volatile(
        "mma.sync.aligned.m16n8k16.row.col.f32.bf16.bf16.f32 "
        "{%0,%1,%2,%3}, {%4,%5,%6,%7}, {%8,%9}, {%0,%1,%2,%3};"
        : "+f"(c[0]), "+f"(c[1]), "+f"(c[2]), "+f"(c[3])
        : "r"(a[0]), "r"(a[1]), "r"(a[2]), "r"(a[3]), "r"(b0), "r"(b1));
}

__device__ __forceinline__ uint32_t packbf(__nv_bfloat16 a, __nv_bfloat16 b) {
    __nv_bfloat162 t(a, b);
    return *reinterpret_cast<uint32_t*>(&t);
}

__device__ __forceinline__ void split2(float x, float y,
                                       uint32_t& hi, uint32_t& lo) {
    __nv_bfloat16 hx = __float2bfloat16(x);
    __nv_bfloat16 hy = __float2bfloat16(y);
    __nv_bfloat16 lx = __float2bfloat16(x - __bfloat162float(hx));
    __nv_bfloat16 ly = __float2bfloat16(y - __bfloat162float(hy));
    hi = packbf(hx, hy);
    lo = packbf(lx, ly);
}

// ---------------------------------------------------------------- bf16 split
__global__ __launch_bounds__(256)
void split_kernel(const float* __restrict__ src,
                  __nv_bfloat16* __restrict__ hi,
                  __nv_bfloat16* __restrict__ lo, int n4)
{
    int i = blockIdx.x * blockDim.x + threadIdx.x;
    if (i >= n4) return;
    float4 v = reinterpret_cast<const float4*>(src)[i];
    uint32_t h0, l0, h1, l1;
    split2(v.x, v.y, h0, l0);
    split2(v.z, v.w, h1, l1);
    uint32_t* hp = reinterpret_cast<uint32_t*>(hi);
    uint32_t* lp = reinterpret_cast<uint32_t*>(lo);
    hp[2 * i] = h0; hp[2 * i + 1] = h1;
    lp[2 * i] = l0; lp[2 * i + 1] = l1;
}

// transpose + split all 4 weights
__global__ __launch_bounds__(256)
void transW_all(const float* __restrict__ w0, const float* __restrict__ w1,
                const float* __restrict__ w2, const float* __restrict__ w3)
{
    __shared__ float tile[32][33];
    int tx = threadIdx.x, ty = threadIdx.y;
    int bx = blockIdx.x * 32, by = blockIdx.y * 32;
    int z = blockIdx.z;
    const float* W = (z == 0) ? w0 : (z == 1) ? w1 : (z == 2) ? w2 : w3;
    __nv_bfloat16* hi = g_Whi[z];
    __nv_bfloat16* lo = g_Wlo[z];
    #pragma unroll
    for (int r = 0; r < 4; r++)
        tile[ty + r * 8][tx] = W[(size_t)(by + ty + r * 8) * E_ + bx + tx];
    __syncthreads();
    #pragma unroll
    for (int r = 0; r < 4; r++) {
        int n = bx + ty + r * 8, k = by + tx;
        float v = tile[tx][ty + r * 8];
        __nv_bfloat16 h = __float2bfloat16(v);
        hi[(size_t)n * E_ + k] = h;
        lo[(size_t)n * E_ + k] = __float2bfloat16(v - __bfloat162float(h));
    }
}

// ---------------------------------------------------------------- prep
__global__ void prep_kernel(const float* __restrict__ rel_emb,
                            const float* __restrict__ bias_k,
                            const float* __restrict__ bias_v)
{
    int i = blockIdx.x * blockDim.x + threadIdx.x;
    if (i < 2048) {
        int rel = i - 1023;
        int bkt = rel > 0 ? 16 : 0;
        int a = rel < 0 ? -rel : rel;
        int bu;
        if (a < 8) {
            bu = a;
        } else {
            float lf = logf((float)a * 0.125f + 1e-6f)
                       * (8.0f / 2.772588722239781f);
            int large = 8 + (int)lf;
            bu = large < 15 ? large : 15;
        }
        int bucket = bkt + bu;
        #pragma unroll
        for (int h = 0; h < NH; h++)
            g_pb[h * 2048 + i] = rel_emb[bucket * NH + h];
    }
    int b = i >> 10, h = (i >> 6) & 15, d = i & 63;
    int x = b * 16 + 15;
    int y = 1009 + h;
    size_t idx = ((size_t)x * SLEN + y) * HD + d;
    float kv = bias_k[h * HD + d];
    float vv = bias_v[h * HD + d];
    __nv_bfloat16 vh = __float2bfloat16(vv);
    g_Kh[idx] = __float2bfloat16(kv);
    g_Vh[idx] = vh;
    g_Vl[idx] = __float2bfloat16(vv - __bfloat162float(vh));
}

// ---------------------------------------------------------------- light GEMM (Q+K)
// 512 threads, 16 warps 8x2, warp 32x64. C = Ahi @ Bhi^T + bias.
// bn 0-7 -> Q (scale + scatter), 8-15 -> K.
__global__ __launch_bounds__(512, 1)
void gemm_qk(const __nv_bfloat16* __restrict__ Ahi,
             const __nv_bfloat16* __restrict__ Bhi,
             const float* __restrict__ q_b,
             const float* __restrict__ k_b)
{
    extern __shared__ __align__(16) char sm_[];
    const int tid = threadIdx.x, lane = tid & 31, w = tid >> 5;
    const int bn = blockIdx.x, bm = blockIdx.y;
    const uint32_t smem_u = cvta_smem(sm_);

    const int wm = w >> 1, wn = w & 1;
    const int m0 = wm * 32, n0 = wn * 64;
    const int gid = lane >> 2, tig = lane & 3;
    const int mat = lane >> 3, rowin = lane & 7;
    const int a_row = rowin + (mat & 1) * 8;
    const int a_kof = (mat >> 1) * 16;
    const int b_row = rowin + (mat >> 1) * 8;
    const int b_kof = (mat & 1) * 16;

    const char* gA0 = (const char*)(Ahi + (size_t)(bm * 256) * 1024);
    const char* gB0 = (const char*)(Bhi + (size_t)(bn * 128) * 1024);

    auto load_l = [&](int it, int buf) {
        uint32_t sb = smem_u + buf * LSTAGE;
        const int kb = it * 64;
        #pragma unroll
        for (int i = 0; i < 3; i++) {
            int idx = tid + i * 512;
            if (idx < 1024) {
                int row = idx >> 2, c = idx & 3;
                CP16(sb + row * GROWB + c * 16,
                     gA0 + (size_t)row * 2048 + kb + c * 16);
            } else {
                int i2 = idx - 1024;
                int row = i2 >> 2, c = i2 & 3;
                CP16(sb + LSB_OFF + row * GROWB + c * 16,
                     gB0 + (size_t)row * 2048 + kb + c * 16);
            }
        }
        CPCOMMIT();
    };

    float acc[2][8][4] = {};
    load_l(0, 0);
    load_l(1, 1);

    for (int it = 0; it < 32; it++) {
        int buf = it % 3;
        if (it < 31) { CPWAIT1(); } else { CPWAIT0(); }
        __syncthreads();
        uint32_t sb = smem_u + buf * LSTAGE;
        #pragma unroll
        for (int ks = 0; ks < 2; ks++) {
            uint32_t ahi[2][4];
            #pragma unroll
            for (int mt = 0; mt < 2; mt++)
                ldsm_x4(ahi[mt], sb + (m0 + mt * 16 + a_row) * GROWB
                                 + ks * 32 + a_kof);
            #pragma unroll
            for (int np = 0; np < 4; np++) {
                uint32_t bhi[4];
                ldsm_x4(bhi, sb + LSB_OFF + (n0 + np * 16 + b_row) * GROWB
                             + ks * 32 + b_kof);
                #pragma unroll
                for (int h = 0; h < 2; h++)
                    #pragma unroll
                    for (int mt = 0; mt < 2; mt++)
                        mma16816(acc[mt][np * 2 + h], ahi[mt],
                                 bhi[2 * h], bhi[2 * h + 1]);
            }
        }
        if (it + 2 < 32) load_l(it + 2, (it + 2) % 3);
    }

    const int sel = bn >> 3;                    // 0=Q, 1=K
    const float* bias = (sel == 0) ? q_b : k_b;
    #pragma unroll
    for (int mt = 0; mt < 2; mt++) {
        #pragma unroll
        for (int nt = 0; nt < 8; nt++) {
            int n = (bn & 7) * 128 + n0 + nt * 8 + tig * 2;
            float bx = bias[n], by = bias[n + 1];
            #pragma unroll
            for (int half = 0; half < 2; half++) {
                int m = bm * 256 + m0 + mt * 16 + gid + half * 8;
                float vx = acc[mt][nt][half * 2 + 0] + bx;
                float vy = acc[mt][nt][half * 2 + 1] + by;
                int t = m >> 2, b = m & 3;
                int h = n >> 6, d = n & 63;
                if (sel == 0) {
                    int x = b * 16 + (t >> 6);
                    int y = ((t & 63) << 4) | h;
                    size_t idx = ((size_t)x * T_ + y) * HD + d;
                    *reinterpret_cast<uint32_t*>(&g_Qh[idx]) =
                        packbf(__float2bfloat16(vx * QSCALE),
                               __float2bfloat16(vy * QSCALE));
                } else {
                    int u = t * 16 + h;
                    int x = b * 16 + u / 1025;
                    int y = u % 1025;
                    size_t idx = ((size_t)x * SLEN + y) * HD + d;
                    *reinterpret_cast<uint32_t*>(&g_Kh[idx]) =
                        packbf(__float2bfloat16(vx), __float2bfloat16(vy));
                }
            }
        }
    }
}

// ---------------------------------------------------------------- heavy GEMM
// 512 threads, 16 warps 8x2, warp 32x64, 3-term bf16 split.
// MODE 2: V proj -> g_Vh/g_Vl scatter. MODE 3: out proj -> Cout.
template<int MODE>
__global__ __launch_bounds__(512, 1)
void gemm_heavy(const __nv_bfloat16* __restrict__ Ahi,
                const __nv_bfloat16* __restrict__ Alo,
                const __nv_bfloat16* __restrict__ Bhi,
                const __nv_bfloat16* __restrict__ Blo,
                const float* __restrict__ bias,
                float* __restrict__ Cout)
{
    extern __shared__ __align__(16) char sm_[];
    const int tid = threadIdx.x, lane = tid & 31, w = tid >> 5;
    const int bn = blockIdx.x, bm = blockIdx.y;
    const uint32_t smem_u = cvta_smem(sm_);

    const int wm = w >> 1, wn = w & 1;
    const int m0 = wm * 32, n0 = wn * 64;
    const int gid = lane >> 2, tig = lane & 3;
    const int mat = lane >> 3, rowin = lane & 7;
    const int a_row = rowin + (mat & 1) * 8;
    const int a_kof = (mat >> 1) * 16;
    const int b_row = rowin + (mat >> 1) * 8;
    const int b_kof = (mat & 1) * 16;

    const char* gA0 = (const char*)(Ahi + (size_t)(bm * 256) * 1024);
    const char* gA1 = (const char*)(Alo + (size_t)(bm * 256) * 1024);
    const char* gB0 = (const char*)(Bhi + (size_t)(bn * 128) * 1024);
    const char* gB1 = (const char*)(Blo + (size_t)(bn * 128) * 1024);

    auto load_stage = [&](int it, int buf) {
        uint32_t sb = smem_u + buf * STAGE;
        const int kb = it * 64;
        #pragma unroll
        for (int i = 0; i < 6; i++) {
            int idx = tid + i * 512;
            if (idx < 2048) {
                int tile = idx >> 10, row = (idx >> 2) & 255, c = idx & 3;
                const char* g = (tile ? gA1 : gA0)
                                + (size_t)row * 2048 + kb + c * 16;
                CP16(sb + tile * SA_SZ + row * GROWB + c * 16, g);
            } else {
                int i2 = idx - 2048;
                int tile = i2 >> 9, row = (i2 >> 2) & 127, c = i2 & 3;
                const char* g = (tile ? gB1 : gB0)
                                + (size_t)row * 2048 + kb + c * 16;
                CP16(sb + SB_OFF + tile * SB_SZ + row * GROWB + c * 16, g);
            }
        }
        CPCOMMIT();
    };

    float acc[2][8][4] = {};
    load_stage(0, 0);
    load_stage(1, 1);

    for (int it = 0; it < 32; it++) {
        int buf = it % 3;
        if (it < 31) { CPWAIT1(); } else { CPWAIT0(); }
        __syncthreads();
        uint32_t sb = smem_u + buf * STAGE;
        #pragma unroll
        for (int ks = 0; ks < 2; ks++) {
            uint32_t ahi[2][4], alo[2][4];
            #pragma unroll
            for (int mt = 0; mt < 2; mt++) {
                uint32_t ar = sb + (m0 + mt * 16 + a_row) * GROWB
                              + ks * 32 + a_kof;
                ldsm_x4(ahi[mt], ar);
                ldsm_x4(alo[mt], ar + SA_SZ);
            }
            #pragma unroll
            for (int np = 0; np < 4; np++) {
                uint32_t br = sb + SB_OFF + (n0 + np * 16 + b_row) * GROWB
                              + ks * 32 + b_kof;
                uint32_t bhi[4], blo[4];
                ldsm_x4(bhi, br);
                ldsm_x4(blo, br + SB_SZ);
                // term-major: maximize gap between same-acc mmas
                #pragma unroll
                for (int h = 0; h < 2; h++)
                    #pragma unroll
                    for (int mt = 0; mt < 2; mt++)
                        mma16816(acc[mt][np * 2 + h], ahi[mt],
                                 bhi[2 * h], bhi[2 * h + 1]);
                #pragma unroll
                for (int h = 0; h < 2; h++)
                    #pragma unroll
                    for (int mt = 0; mt < 2; mt++)
                        mma16816(acc[mt][np * 2 + h], ahi[mt],
                                 blo[2 * h], blo[2 * h + 1]);
                #pragma unroll
                for (int h = 0; h < 2; h++)
                    #pragma unroll
                    for (int mt = 0; mt < 2; mt++)
                        mma16816(acc[mt][np * 2 + h], alo[mt],
                                 bhi[2 * h], bhi[2 * h + 1]);
            }
        }
        if (it + 2 < 32) load_stage(it + 2, (it + 2) % 3);
    }

    #pragma unroll
    for (int mt = 0; mt < 2; mt++) {
        #pragma unroll
        for (int nt = 0; nt < 8; nt++) {
            int n = bn * 128 + n0 + nt * 8 + tig * 2;
            float bx = bias[n], by = bias[n + 1];
            #pragma unroll
            for (int half = 0; half < 2; half++) {
                int m = bm * 256 + m0 + mt * 16 + gid + half * 8;
                float vx = acc[mt][nt][half * 2 + 0] + bx;
                float vy = acc[mt][nt][half * 2 + 1] + by;
                if (MODE == 3) {
                    *reinterpret_cast<float2*>(&Cout[(size_t)m * E_ + n]) =
                        make_float2(vx, vy);
                } else {
                    int t = m >> 2, b = m & 3;
                    int h = n >> 6, d = n & 63;
                    int u = t * 16 + h;
                    int x = b * 16 + u / 1025;
                    int y = u % 1025;
                    size_t idx = ((size_t)x * SLEN + y) * HD + d;
                    uint32_t hi, lo;
                    split2(vx, vy, hi, lo);
                    *reinterpret_cast<uint32_t*>(&g_Vh[idx]) = hi;
                    *reinterpret_cast<uint32_t*>(&g_Vl[idx]) = lo;
                }
            }
        }
    }
}

// ---------------------------------------------------------------- attention
// (unchanged from R7)
__global__ __launch_bounds__(128, 3)
void attn_mma(const float* __restrict__ grep_w,
              const float* __restrict__ grep_b,
              const float* __restrict__ grep_a)
{
    extern __shared__ __align__(16) char asmm[];
    const uint32_t smem_u = cvta_smem(asmm);
    const int tid = threadIdx.x, lane = tid & 31, w = tid >> 5;
    const int gid = lane >> 2, tig = lane & 3;
    const int mat = lane >> 3, rowin = lane & 7;
    const int x = blockIdx.y, t0 = blockIdx.x * 64;
    const int hx = x & 15, bx = x >> 4;

    float* gate_s = reinterpret_cast<float*>(asmm + A_GT);
    float* gws_s  = gate_s + 64;
    float* misc_s = gws_s + 64;

    if (tid < 64) {
        float s = 0.f;
        #pragma unroll
        for (int j = 0; j < 8; j++) s += grep_w[tid * 8 + j];
        gws_s[tid] = s;
    }
    if (tid == 64) {
        float s = 0.f;
        #pragma unroll
        for (int j = 0; j < 8; j++) s += grep_b[j];
        misc_s[0] = s;
    }
    if (tid == 65) misc_s[1] = grep_a[hx];

    {
        const char* srcH = (const char*)g_Qh + ((size_t)x * T_ + t0) * HD * 2;
        #pragma unroll
        for (int i = 0; i < 4; i++) {
            int idx = tid + i * 128;
            int row = idx >> 3, c = idx & 7;
            CP16(smem_u + row * AROW + c * 16,
                 srcH + (size_t)row * 128 + c * 16);
        }
        CPCOMMIT();
    }

    const char* pKh = (const char*)g_Kh + (size_t)x * SLEN * HD * 2;
    const char* pVh = (const char*)g_Vh + (size_t)x * SLEN * HD * 2;
    const char* pVl = (const char*)g_Vl + (size_t)x * SLEN * HD * 2;

    auto load_kv = [&](int ch, int buf) {
        int s0 = ch * 64;
        #pragma unroll
        for (int i = 0; i < 12; i++) {
            int idx = tid + i * 128;
            int tile = idx >> 9, row = (idx >> 3) & 63, c = idx & 7;
            const char* p = (tile == 0) ? pKh : (tile == 1) ? pVh : pVl;
            CP16(smem_u + A_ST + buf * A_STB + tile * ATILE
                 + row * AROW + c * 16,
                 p + (size_t)(s0 + row) * 128 + c * 16);
        }
        CPCOMMIT();
    };

    load_kv(0, 0);

    CPWAIT1();
    __syncthreads();
    {
        int r = tid >> 1, hf = tid & 1;
        const __nv_bfloat16* qr =
            reinterpret_cast<const __nv_bfloat16*>(asmm + r * AROW) + hf * 32;
        float s = 0.f;
        #pragma unroll
        for (int d2 = 0; d2 < 32; d2++)
            s += __bfloat162float(qr[d2]) * gws_s[hf * 32 + d2];
        s += __shfl_xor_sync(0xffffffffu, s, 1);
        if (hf == 0)
            gate_s[r] = misc_s[1] / (1.f + __expf(-(s * 256.f + misc_s[0])));
    }

    float m0 = -1e30f, m1 = -1e30f, l0 = 0.f, l1 = 0.f;
    float o[8][4] = {};
    uint32_t qh[4][4];
    const int tg0 = t0 + w * 16 + gid;
    float gate0 = 0.f, gate1 = 0.f;

    for (int ch = 0; ch < 17; ch++) {
        int buf = ch & 1;
        if (ch + 1 < 17) { load_kv(ch + 1, buf ^ 1); CPWAIT1(); }
        else             { CPWAIT0(); }
        __syncthreads();

        if (ch == 0) {
            #pragma unroll
            for (int ks = 0; ks < 4; ks++)
                ldsm_x4(qh[ks], smem_u
                        + (w * 16 + rowin + (mat & 1) * 8) * AROW
                        + ks * 32 + (mat >> 1) * 16);
            gate0 = gate_s[w * 16 + gid];
            gate1 = gate_s[w * 16 + gid + 8];
        }

        const uint32_t kb = smem_u + A_ST + buf * A_STB;

        float s_acc[8][4] = {};
        #pragma unroll
        for (int ks = 0; ks < 4; ks++) {
            #pragma unroll
            for (int np = 0; np < 4; np++) {
                uint32_t khf[4];
                ldsm_x4(khf, kb + (np * 16 + rowin + (mat >> 1) * 8) * AROW
                             + ks * 32 + (mat & 1) * 16);
                #pragma unroll
                for (int h2 = 0; h2 < 2; h2++)
                    mma16816(s_acc[np * 2 + h2], qh[ks],
                             khf[2 * h2], khf[2 * h2 + 1]);
            }
        }

        int s0 = ch * 64;
        #pragma unroll
        for (int nt = 0; nt < 8; nt++) {
            #pragma unroll
            for (int j = 0; j < 4; j++) {
                int sg = s0 + nt * 8 + tig * 2 + (j & 1);
                int tg = tg0 + (j >> 1) * 8;
                float g = (j >> 1) ? gate1 : gate0;
                if (sg < SLEN)
                    s_acc[nt][j] += g * __ldg(&g_pb[hx * 2048 + sg - tg + 1023]);
                else
                    s_acc[nt][j] = -1e30f;
            }
        }

        float mx0 = -1e30f, mx1 = -1e30f;
        #pragma unroll
        for (int nt = 0; nt < 8; nt++) {
            mx0 = fmaxf(mx0, fmaxf(s_acc[nt][0], s_acc[nt][1]));
            mx1 = fmaxf(mx1, fmaxf(s_acc[nt][2], s_acc[nt][3]));
        }
        mx0 = fmaxf(mx0, __shfl_xor_sync(0xffffffffu, mx0, 1));
        mx0 = fmaxf(mx0, __shfl_xor_sync(0xffffffffu, mx0, 2));
        mx1 = fmaxf(mx1, __shfl_xor_sync(0xffffffffu, mx1, 1));
        mx1 = fmaxf(mx1, __shfl_xor_sync(0xffffffffu, mx1, 2));
        float mn0 = fmaxf(m0, mx0), mn1 = fmaxf(m1, mx1);
        float al0 = __expf(m0 - mn0), al1 = __expf(m1 - mn1);
        m0 = mn0; m1 = mn1;

        float sum0 = 0.f, sum1 = 0.f;
        #pragma unroll
        for (int nt = 0; nt < 8; nt++) {
            float p0 = __expf(s_acc[nt][0] - mn0);
            float p1 = __expf(s_acc[nt][1] - mn0);
            float p2 = __expf(s_acc[nt][2] - mn1);
            float p3 = __expf(s_acc[nt][3] - mn1);
            s_acc[nt][0] = p0; s_acc[nt][1] = p1;
            s_acc[nt][2] = p2; s_acc[nt][3] = p3;
            sum0 += p0 + p1; sum1 += p2 + p3;
        }
        sum0 += __shfl_xor_sync(0xffffffffu, sum0, 1);
        sum0 += __shfl_xor_sync(0xffffffffu, sum0, 2);
        sum1 += __shfl_xor_sync(0xffffffffu, sum1, 1);
        sum1 += __shfl_xor_sync(0xffffffffu, sum1, 2);
        l0 = l0 * al0 + sum0;
        l1 = l1 * al1 + sum1;

        #pragma unroll
        for (int nt = 0; nt < 8; nt++) {
            o[nt][0] *= al0; o[nt][1] *= al0;
            o[nt][2] *= al1; o[nt][3] *= al1;
        }

        const uint32_t vbh = kb + ATILE;
        const uint32_t vbl = kb + 2 * ATILE;
        #pragma unroll
        for (int ks = 0; ks < 4; ks++) {
            uint32_t ah[4], al[4];
            #pragma unroll
            for (int q = 0; q < 4; q++) {
                int nt = 2 * ks + (q >> 1);
                split2(s_acc[nt][(q & 1) * 2], s_acc[nt][(q & 1) * 2 + 1],
                       ah[q], al[q]);
            }
            #pragma unroll
            for (int np = 0; np < 4; np++) {
                uint32_t va_off = (ks * 16 + rowin + (mat & 1) * 8) * AROW
                                  + (np * 16 + (mat >> 1) * 8) * 2;
                uint32_t vhf[4], vlf[4];
                ldsm_x4_t(vhf, vbh + va_off);
                ldsm_x4_t(vlf, vbl + va_off);
                #pragma unroll
                for (int h2 = 0; h2 < 2; h2++)
                    mma16816(o[np * 2 + h2], ah, vhf[2 * h2], vhf[2 * h2 + 1]);
                #pragma unroll
                for (int h2 = 0; h2 < 2; h2++)
                    mma16816(o[np * 2 + h2], ah, vlf[2 * h2], vlf[2 * h2 + 1]);
                #pragma unroll
                for (int h2 = 0; h2 < 2; h2++)
                    mma16816(o[np * 2 + h2], al, vhf[2 * h2], vhf[2 * h2 + 1]);
            }
        }
        __syncthreads();
    }

    float inv0 = 1.0f / l0, inv1 = 1.0f / l1;
    int y0 = tg0, y1 = tg0 + 8;
    #pragma unroll
    for (int nt = 0; nt < 8; nt++) {
        int col = hx * 64 + nt * 8 + tig * 2;
        uint32_t hi, lo;
        split2(o[nt][0] * inv0, o[nt][1] * inv0, hi, lo);
        size_t i0 = (size_t)(y0 * BZ + bx) * E_ + col;
        *reinterpret_cast<uint32_t*>(&g_Ahi[i0]) = hi;
        *reinterpret_cast<uint32_t*>(&g_Alo[i0]) = lo;
        split2(o[nt][2] * inv1, o[nt][3] * inv1, hi, lo);
        size_t i1 = (size_t)(y1 * BZ + bx) * E_ + col;
        *reinterpret_cast<uint32_t*>(&g_Ahi[i1]) = hi;
        *reinterpret_cast<uint32_t*>(&g_Alo[i1]) = lo;
    }
}

// ---------------------------------------------------------------- host side
extern "C" void kernel_launch(void* const* d_in, const int* in_sizes, int n_in,
                              void* d_out, int out_size)
{
    (void)in_sizes; (void)n_in; (void)out_size;
    const float* query   = (const float*)d_in[0];
    const float* q_w     = (const float*)d_in[1];
    const float* q_b     = (const float*)d_in[2];
    const float* k_w     = (const float*)d_in[3];
    const float* k_b     = (const float*)d_in[4];
    const float* v_w     = (const float*)d_in[5];
    const float* v_b     = (const float*)d_in[6];
    const float* out_w   = (const float*)d_in[7];
    const float* out_b   = (const float*)d_in[8];
    const float* rel_emb = (const float*)d_in[9];
    const float* grep_w  = (const float*)d_in[10];
    const float* grep_b  = (const float*)d_in[11];
    const float* grep_a  = (const float*)d_in[12];
    const float* bias_k  = (const float*)d_in[13];
    const float* bias_v  = (const float*)d_in[14];
    float* out = (float*)d_out;

    void *pAhi, *pAlo, *pWhi, *pWlo;
    cudaGetSymbolAddress(&pAhi, g_Ahi);
    cudaGetSymbolAddress(&pAlo, g_Alo);
    cudaGetSymbolAddress(&pWhi, g_Whi);
    cudaGetSymbolAddress(&pWlo, g_Wlo);

    __nv_bfloat16* Ahi = (__nv_bfloat16*)pAhi;
    __nv_bfloat16* Alo = (__nv_bfloat16*)pAlo;
    const size_t wsz = (size_t)E_ * E_;
    __nv_bfloat16* Whi = (__nv_bfloat16*)pWhi;
    __nv_bfloat16* Wlo = (__nv_bfloat16*)pWlo;

    cudaFuncSetAttribute((const void*)gemm_qk,
        cudaFuncAttributeMaxDynamicSharedMemorySize, LGEMM_SMEM);
    cudaFuncSetAttribute((const void*)gemm_heavy<2>,
        cudaFuncAttributeMaxDynamicSharedMemorySize, GEMM_SMEM);
    cudaFuncSetAttribute((const void*)gemm_heavy<3>,
        cudaFuncAttributeMaxDynamicSharedMemorySize, GEMM_SMEM);
    cudaFuncSetAttribute((const void*)attn_mma,
        cudaFuncAttributeMaxDynamicSharedMemorySize, ATTN_SMEM);

    // slot 4 = heavy V gemm (ncu capture position)
    split_kernel<<<4096, 256>>>(query, Ahi, Alo, M_ * E_ / 4);          // 1
    transW_all<<<dim3(32, 32, 4), dim3(32, 8)>>>(q_w, k_w, v_w, out_w); // 2
    prep_kernel<<<16, 256>>>(rel_emb, bias_k, bias_v);                  // 3
    gemm_heavy<2><<<dim3(8, 16), 512, GEMM_SMEM>>>(                     // 4
        Ahi, Alo, Whi + 2 * wsz, Wlo + 2 * wsz, v_b, nullptr);
    gemm_qk<<<dim3(16, 16), 512, LGEMM_SMEM>>>(Ahi, Whi, q_b, k_b);     // 5
    attn_mma<<<dim3(16, 64), 128, ATTN_SMEM>>>(grep_w, grep_b, grep_a); // 6
    gemm_heavy<3><<<dim3(8, 16), 512, GEMM_SMEM>>>(                     // 7
        Ahi, Alo, Whi + 3 * wsz, Wlo + 3 * wsz, out_b, out);
}